// round 7
// baseline (speedup 1.0000x reference)
#include <cuda_runtime.h>
#include <cuda_bf16.h>
#include <cstdint>

#define B_  4
#define T_  2048
#define C_  1024
#define H_  16
#define HS_ 64

// ---------------------------------------------------------------------------
// Scratch (allocation-free rule: __device__ globals)
// ---------------------------------------------------------------------------
__device__ __nv_bfloat16 g_xhi[B_ * T_ * C_];
__device__ __nv_bfloat16 g_xlo[B_ * T_ * C_];
__device__ __nv_bfloat16 g_wthi[3 * H_ * HS_ * C_];   // [n=z*64+d][c] K-major
__device__ __nv_bfloat16 g_wtlo[3 * H_ * HS_ * C_];
__device__ __nv_bfloat16 g_wohi[C_ * C_];             // [n][k]
__device__ __nv_bfloat16 g_wolo[C_ * C_];
__device__ __nv_bfloat16 g_ahi[B_ * T_ * C_];
__device__ __nv_bfloat16 g_alo[B_ * T_ * C_];

// q/k/v in bf16 hi/lo, layout [bh][t][64]; q pre-scaled by 1/sqrt(HS)
__device__ __nv_bfloat16 g_qh[B_ * H_ * T_ * HS_];
__device__ __nv_bfloat16 g_ql[B_ * H_ * T_ * HS_];
__device__ __nv_bfloat16 g_kh[B_ * H_ * T_ * HS_];
__device__ __nv_bfloat16 g_kl[B_ * H_ * T_ * HS_];
__device__ __nv_bfloat16 g_vh[B_ * H_ * T_ * HS_];
__device__ __nv_bfloat16 g_vl[B_ * H_ * T_ * HS_];

// ---------------------------------------------------------------------------
// Portable tensor-core primitives (sm_80+ ISA; compiles at base compute_103)
// ---------------------------------------------------------------------------
__device__ __forceinline__ uint32_t smem_u32(const void* p) {
    uint32_t a;
    asm("{ .reg .u64 t; cvta.to.shared.u64 t, %1; cvt.u32.u64 %0, t; }"
        : "=r"(a) : "l"(p));
    return a;
}

__device__ __forceinline__ void ldsm4(uint32_t* r, uint32_t addr) {
    asm volatile("ldmatrix.sync.aligned.m8n8.x4.shared.b16 {%0,%1,%2,%3}, [%4];"
        : "=r"(r[0]), "=r"(r[1]), "=r"(r[2]), "=r"(r[3]) : "r"(addr));
}

__device__ __forceinline__ void ldsm4t(uint32_t* r, uint32_t addr) {
    asm volatile("ldmatrix.sync.aligned.m8n8.x4.trans.shared.b16 {%0,%1,%2,%3}, [%4];"
        : "=r"(r[0]), "=r"(r[1]), "=r"(r[2]), "=r"(r[3]) : "r"(addr));
}

__device__ __forceinline__ void mma16816(float* c, const uint32_t* a,
                                         const uint32_t b0, const uint32_t b1) {
    asm volatile(
        "mma.sync.aligned.m16n8k16.row.col.f32.bf16.bf16.f32 "
        "{%0,%1,%2,%3}, {%4,%5,%6,%7}, {%8,%9}, {%0,%1,%2,%3};"
        : "+f"(c[0]), "+f"(c[1]), "+f"(c[2]), "+f"(c[3])
        : "r"(a[0]), "r"(a[1]), "r"(a[2]), "r"(a[3]), "r"(b0), "r"(b1));
}

__device__ __forceinline__ uint32_t packbf(float a, float b) {
    __nv_bfloat162 t = __floats2bfloat162_rn(a, b);
    return *(uint32_t*)&t;
}

__device__ __forceinline__ void cp16(uint32_t dst, const void* src) {
    asm volatile("cp.async.cg.shared.global [%0], [%1], 16;"
        :: "r"(dst), "l"(src) : "memory");
}
#define CP_COMMIT() asm volatile("cp.async.commit_group;" ::: "memory")
#define CP_WAIT(n)  asm volatile("cp.async.wait_group %0;" :: "n"(n) : "memory")

// ---------------------------------------------------------------------------
// fp32 -> bf16 hi/lo split kernels
// ---------------------------------------------------------------------------
struct __align__(8) bf4 { __nv_bfloat16 a, b, c, d; };

__device__ __forceinline__ void split4(float4 v, bf4& hv, bf4& lv) {
    __nv_bfloat16 h0 = __float2bfloat16(v.x);
    __nv_bfloat16 h1 = __float2bfloat16(v.y);
    __nv_bfloat16 h2 = __float2bfloat16(v.z);
    __nv_bfloat16 h3 = __float2bfloat16(v.w);
    hv = {h0, h1, h2, h3};
    lv = {__float2bfloat16(v.x - __bfloat162float(h0)),
          __float2bfloat16(v.y - __bfloat162float(h1)),
          __float2bfloat16(v.z - __bfloat162float(h2)),
          __float2bfloat16(v.w - __bfloat162float(h3))};
}

__global__ __launch_bounds__(256) void split_kernel(
    const float* __restrict__ in,
    __nv_bfloat16* __restrict__ hi,
    __nv_bfloat16* __restrict__ lo, int n4)
{
    int i = blockIdx.x * blockDim.x + threadIdx.x;
    if (i >= n4) return;
    bf4 hv, lv;
    split4(((const float4*)in)[i], hv, lv);
    ((bf4*)hi)[i] = hv;
    ((bf4*)lo)[i] = lv;
}

// W[h][c][d] (fp32) -> Wt[z][d][c] (bf16 hi/lo), z = p*16+h
__global__ __launch_bounds__(256) void split_wqkv_kernel(
    const float* __restrict__ Wq,
    const float* __restrict__ Wk,
    const float* __restrict__ Wv)
{
    int z = blockIdx.y;
    int p = z >> 4, h = z & 15;
    const float* W = (p == 0 ? Wq : (p == 1 ? Wk : Wv)) + (size_t)h * C_ * HS_;
    int idx = blockIdx.x * blockDim.x + threadIdx.x;
    int d = idx & 63;
    int c = idx >> 6;
    float v = W[(size_t)c * HS_ + d];
    __nv_bfloat16 hv = __float2bfloat16(v);
    __nv_bfloat16 lv = __float2bfloat16(v - __bfloat162float(hv));
    size_t o = ((size_t)z * HS_ + d) * C_ + c;
    g_wthi[o] = hv;
    g_wtlo[o] = lv;
}

// ---------------------------------------------------------------------------
// Pipelined HMMA GEMM: CTA 128x128, warp tile 64x32 (8 warps, 2x4), BK=32,
// 2-stage cp.async double buffering. A,B K-major bf16 hi/lo.
// smem per stage: Ah,Al,Bh,Bl each 128 rows x 80B = 10240B; stage = 40960B.
// ---------------------------------------------------------------------------
#define GSTR    80
#define OFF_AH  0
#define OFF_AL  10240
#define OFF_BH  20480
#define OFF_BL  30720
#define STG_SZ  40960
#define GSMEM   (2 * STG_SZ)   // 81920

__device__ __forceinline__ void stage_load(
    uint32_t sbase,
    const __nv_bfloat16* __restrict__ Ah, const __nv_bfloat16* __restrict__ Al,
    const __nv_bfloat16* __restrict__ Bh, const __nv_bfloat16* __restrict__ Bl,
    int a_row0, int b_row0, int k0, int t)
{
    const int row = t >> 1;
    const int cb  = (t & 1) * 32;            // byte offset within 64B row
    const uint32_t so = (uint32_t)row * GSTR + cb;
    const size_t ga = (size_t)(a_row0 + row) * C_ + k0 + (cb >> 1);
    const size_t gb = (size_t)(b_row0 + row) * C_ + k0 + (cb >> 1);
    cp16(sbase + OFF_AH + so,      Ah + ga);
    cp16(sbase + OFF_AH + so + 16, Ah + ga + 8);
    cp16(sbase + OFF_AL + so,      Al + ga);
    cp16(sbase + OFF_AL + so + 16, Al + ga + 8);
    cp16(sbase + OFF_BH + so,      Bh + gb);
    cp16(sbase + OFF_BH + so + 16, Bh + gb + 8);
    cp16(sbase + OFF_BL + so,      Bl + gb);
    cp16(sbase + OFF_BL + so + 16, Bl + gb + 8);
}

__device__ __forceinline__ void stage_compute(
    uint32_t sbase, const uint32_t aoff[4], const uint32_t boff[2],
    float acc[4][4][4])
{
    #pragma unroll
    for (int kk = 0; kk < 2; kk++) {
        const uint32_t kb = (uint32_t)kk * 32;
        uint32_t ah[4][4], al[4][4];
        #pragma unroll
        for (int mt = 0; mt < 4; mt++) {
            ldsm4(ah[mt], sbase + OFF_AH + aoff[mt] + kb);
            ldsm4(al[mt], sbase + OFF_AL + aoff[mt] + kb);
        }
        #pragma unroll
        for (int np = 0; np < 2; np++) {
            uint32_t bh[4], bl[4];
            ldsm4(bh, sbase + OFF_BH + boff[np] + kb);
            ldsm4(bl, sbase + OFF_BL + boff[np] + kb);
            #pragma unroll
            for (int mt = 0; mt < 4; mt++)
                #pragma unroll
                for (int hf = 0; hf < 2; hf++) {
                    const int nt = np * 2 + hf;
                    mma16816(acc[mt][nt], ah[mt], bh[hf * 2], bh[hf * 2 + 1]);
                    mma16816(acc[mt][nt], ah[mt], bl[hf * 2], bl[hf * 2 + 1]);
                    mma16816(acc[mt][nt], al[mt], bh[hf * 2], bh[hf * 2 + 1]);
                }
        }
    }
}

__device__ __forceinline__ void gemm_mainloop(
    const __nv_bfloat16* __restrict__ Ah, const __nv_bfloat16* __restrict__ Al,
    const __nv_bfloat16* __restrict__ Bh, const __nv_bfloat16* __restrict__ Bl,
    int a_row0, int b_row0, uint32_t sb, float acc[4][4][4])
{
    const int t = threadIdx.x;
    const int wid = t >> 5, lane = t & 31;
    const int warp_m = wid & 1, warp_n = wid >> 1;
    const int g = lane >> 3, lr = lane & 7;

    uint32_t aoff[4], boff[2];
    #pragma unroll
    for (int mt = 0; mt < 4; mt++)
        aoff[mt] = (uint32_t)(warp_m * 64 + mt * 16 + (g & 1) * 8 + lr) * GSTR
                 + (uint32_t)(g >> 1) * 16;
    #pragma unroll
    for (int np = 0; np < 2; np++)
        boff[np] = (uint32_t)(warp_n * 32 + np * 16 + (g >> 1) * 8 + lr) * GSTR
                 + (uint32_t)(g & 1) * 16;

    #pragma unroll
    for (int mt = 0; mt < 4; mt++)
        #pragma unroll
        for (int nt = 0; nt < 4; nt++)
            #pragma unroll
            for (int i = 0; i < 4; i++) acc[mt][nt][i] = 0.f;

    const int NCH = C_ / 32;   // 32 chunks
    stage_load(sb, Ah, Al, Bh, Bl, a_row0, b_row0, 0, t);
    CP_COMMIT();
    for (int i = 0; i < NCH; i++) {
        const uint32_t scur = sb + (uint32_t)(i & 1) * STG_SZ;
        if (i + 1 < NCH) {
            stage_load(sb + (uint32_t)((i + 1) & 1) * STG_SZ,
                       Ah, Al, Bh, Bl, a_row0, b_row0, (i + 1) * 32, t);
            CP_COMMIT();
            CP_WAIT(1);
        } else {
            CP_WAIT(0);
        }
        __syncthreads();
        stage_compute(scur, aoff, boff, acc);
        __syncthreads();
    }
}

// Fused QKV GEMM: [8192,1024] @ [1024,3072]; grid (64, 24), block 256.
// Epilogue -> g_{q,k,v}{h,l} bf16 hi/lo, q scaled by 1/8.
__global__ __launch_bounds__(256) void qkv_mma_kernel()
{
    extern __shared__ __align__(16) unsigned char dynsmem[];
    const uint32_t sb = smem_u32(dynsmem);
    const int m0 = blockIdx.x * 128;
    const int n0 = blockIdx.y * 128;

    float acc[4][4][4];
    gemm_mainloop(g_xhi, g_xlo, g_wthi, g_wtlo, m0, n0, sb, acc);

    const int wid = threadIdx.x >> 5, lane = threadIdx.x & 31;
    const int warp_m = wid & 1, warp_n = wid >> 1;
    const int qr = lane >> 2, qc2 = (lane & 3) * 2;

    #pragma unroll
    for (int nt = 0; nt < 4; nt++) {
        const int gn = n0 + warp_n * 32 + nt * 8 + qc2;
        const int z = gn >> 6, d = gn & 63;
        const int p = z >> 4, h = z & 15;
        __nv_bfloat16* outh = (p == 0 ? g_qh : (p == 1 ? g_kh : g_vh));
        __nv_bfloat16* outl = (p == 0 ? g_ql : (p == 1 ? g_kl : g_vl));
        const float scale = (p == 0) ? 0.125f : 1.0f;
        #pragma unroll
        for (int mt = 0; mt < 4; mt++) {
            #pragma unroll
            for (int rh = 0; rh < 2; rh++) {
                const int gm = m0 + warp_m * 64 + mt * 16 + qr + rh * 8;
                const int b = gm >> 11, tt = gm & (T_ - 1);
                const size_t idx = ((size_t)(b * H_ + h) * T_ + tt) * HS_ + d;
                float v0 = acc[mt][nt][rh * 2] * scale;
                float v1 = acc[mt][nt][rh * 2 + 1] * scale;
                float h0 = __bfloat162float(__float2bfloat16(v0));
                float h1 = __bfloat162float(__float2bfloat16(v1));
                *(uint32_t*)&outh[idx] = packbf(h0, h1);
                *(uint32_t*)&outl[idx] = packbf(v0 - h0, v1 - h1);
            }
        }
    }
}

// Output projection: [8192,1024] @ [1024,1024]; grid (64, 8), block 256.
__global__ __launch_bounds__(256) void proj_mma_kernel(
    const float* __restrict__ bo, float* __restrict__ out)
{
    extern __shared__ __align__(16) unsigned char dynsmem[];
    const uint32_t sb = smem_u32(dynsmem);
    const int m0 = blockIdx.x * 128;
    const int n0 = blockIdx.y * 128;

    float acc[4][4][4];
    gemm_mainloop(g_ahi, g_alo, g_wohi, g_wolo, m0, n0, sb, acc);

    const int wid = threadIdx.x >> 5, lane = threadIdx.x & 31;
    const int warp_m = wid & 1, warp_n = wid >> 1;
    const int qr = lane >> 2, qc2 = (lane & 3) * 2;

    #pragma unroll
    for (int nt = 0; nt < 4; nt++) {
        const int gn = n0 + warp_n * 32 + nt * 8 + qc2;
        const float2 bb = *(const float2*)&bo[gn];
        #pragma unroll
        for (int mt = 0; mt < 4; mt++) {
            #pragma unroll
            for (int rh = 0; rh < 2; rh++) {
                const int gm = m0 + warp_m * 64 + mt * 16 + qr + rh * 8;
                *(float2*)(out + (size_t)gm * C_ + gn) =
                    make_float2(acc[mt][nt][rh * 2] + bb.x,
                                acc[mt][nt][rh * 2 + 1] + bb.y);
            }
        }
    }
}

// ---------------------------------------------------------------------------
// HMMA causal flash attention (unchanged from R6 — passing at rel_err 1.16e-5)
// ---------------------------------------------------------------------------
#define QSTR 144
#define SQ_  (64 * QSTR)
#define SKV_ (64 * QSTR)

__global__ __launch_bounds__(128) void attn_hmma_kernel()
{
    __shared__ __align__(16) unsigned char smem[2 * SQ_ + 4 * SKV_];
    unsigned char* sQh = smem;
    unsigned char* sQl = smem + SQ_;
    unsigned char* sKh = smem + 2 * SQ_;
    unsigned char* sKl = sKh + SKV_;
    unsigned char* sVh = sKl + SKV_;
    unsigned char* sVl = sVh + SKV_;
    const uint32_t uQh = smem_u32(sQh), uQl = smem_u32(sQl);
    const uint32_t uKh = smem_u32(sKh), uKl = smem_u32(sKl);
    const uint32_t uVh = smem_u32(sVh), uVl = smem_u32(sVl);

    const int bh = blockIdx.y;
    const int r0 = blockIdx.x * 64;
    const int t  = threadIdx.x;
    const int w  = t >> 5, lane = t & 31;
    const int g = lane >> 3, lr = lane & 7;
    const int qr = lane >> 2, qc = lane & 3;

    const size_t base = (size_t)bh * T_ * HS_;

    const int crow = t >> 1;
    const int coff = (t & 1) * 64;

    {
        const unsigned char* gh =
            (const unsigned char*)(g_qh + base + (size_t)(r0 + crow) * HS_) + coff;
        const unsigned char* gl =
            (const unsigned char*)(g_ql + base + (size_t)(r0 + crow) * HS_) + coff;
        uint4 a0 = ((const uint4*)gh)[0], a1 = ((const uint4*)gh)[1];
        uint4 a2 = ((const uint4*)gh)[2], a3 = ((const uint4*)gh)[3];
        uint4 b0 = ((const uint4*)gl)[0], b1 = ((const uint4*)gl)[1];
        uint4 b2 = ((const uint4*)gl)[2], b3 = ((const uint4*)gl)[3];
        uint4* dh = (uint4*)(sQh + crow * QSTR + coff);
        uint4* dl = (uint4*)(sQl + crow * QSTR + coff);
        dh[0] = a0; dh[1] = a1; dh[2] = a2; dh[3] = a3;
        dl[0] = b0; dl[1] = b1; dl[2] = b2; dl[3] = b3;
    }
    __syncthreads();

    uint32_t qh[4][4], ql[4][4];
    {
        const uint32_t qoff = (uint32_t)(w * 16 + (g & 1) * 8 + lr) * QSTR
                            + (uint32_t)((g >> 1) * 8) * 2;
        #pragma unroll
        for (int ks = 0; ks < 4; ks++) {
            ldsm4(qh[ks], uQh + qoff + ks * 32);
            ldsm4(ql[ks], uQl + qoff + ks * 32);
        }
    }

    float accO[8][4];
    #pragma unroll
    for (int nt = 0; nt < 8; nt++)
        #pragma unroll
        for (int i = 0; i < 4; i++) accO[nt][i] = 0.f;
    float mrow[2] = {-1e30f, -1e30f};
    float lrow[2] = {0.f, 0.f};

    uint32_t koff[4];
    #pragma unroll
    for (int np = 0; np < 4; np++)
        koff[np] = (uint32_t)(np * 16 + (g >> 1) * 8 + lr) * QSTR
                 + (uint32_t)((g & 1) * 8) * 2;
    const uint32_t vrow = (uint32_t)((g & 1) * 8 + lr);
    const uint32_t vcol = (uint32_t)((g >> 1) * 8) * 2;

    for (int j0 = 0; j0 <= r0; j0 += 64) {
        __syncthreads();
        {
            const unsigned char* pkh =
                (const unsigned char*)(g_kh + base + (size_t)(j0 + crow) * HS_) + coff;
            const unsigned char* pkl =
                (const unsigned char*)(g_kl + base + (size_t)(j0 + crow) * HS_) + coff;
            const unsigned char* pvh =
                (const unsigned char*)(g_vh + base + (size_t)(j0 + crow) * HS_) + coff;
            const unsigned char* pvl =
                (const unsigned char*)(g_vl + base + (size_t)(j0 + crow) * HS_) + coff;
            uint4 kh0 = ((const uint4*)pkh)[0], kh1 = ((const uint4*)pkh)[1];
            uint4 kh2 = ((const uint4*)pkh)[2], kh3 = ((const uint4*)pkh)[3];
            uint4 kl0 = ((const uint4*)pkl)[0], kl1 = ((const uint4*)pkl)[1];
            uint4 kl2 = ((const uint4*)pkl)[2], kl3 = ((const uint4*)pkl)[3];
            uint4 vh0 = ((const uint4*)pvh)[0], vh1 = ((const uint4*)pvh)[1];
            uint4 vh2 = ((const uint4*)pvh)[2], vh3 = ((const uint4*)pvh)[3];
            uint4 vl0 = ((const uint4*)pvl)[0], vl1 = ((const uint4*)pvl)[1];
            uint4 vl2 = ((const uint4*)pvl)[2], vl3 = ((const uint4*)pvl)[3];
            const uint32_t doff = crow * QSTR + coff;
            uint4* dkh = (uint4*)(sKh + doff);
            uint4* dkl = (uint4*)(sKl + doff);
            uint4* dvh = (uint4*)(sVh + doff);
            uint4* dvl = (uint4*)(sVl + doff);
            dkh[0] = kh0; dkh[1] = kh1; dkh[2] = kh2; dkh[3] = kh3;
            dkl[0] = kl0; dkl[1] = kl1; dkl[2] = kl2; dkl[3] = kl3;
            dvh[0] = vh0; dvh[1] = vh1; dvh[2] = vh2; dvh[3] = vh3;
            dvl[0] = vl0; dvl[1] = vl1; dvl[2] = vl2; dvl[3] = vl3;
        }
        __syncthreads();

        float accS[8][4];
        #pragma unroll
        for (int nt = 0; nt < 8; nt++)
            #pragma unroll
            for (int i = 0; i < 4; i++) accS[nt][i] = 0.f;

        #pragma unroll
        for (int ks = 0; ks < 4; ks++) {
            #pragma unroll
            for (int np = 0; np < 4; np++) {
                uint32_t kfh[4], kfl[4];
                ldsm4(kfh, uKh + koff[np] + ks * 32);
                ldsm4(kfl, uKl + koff[np] + ks * 32);
                #pragma unroll
                for (int hf = 0; hf < 2; hf++) {
                    const int nt = np * 2 + hf;
                    mma16816(accS[nt], qh[ks], kfh[hf * 2], kfh[hf * 2 + 1]);
                    mma16816(accS[nt], qh[ks], kfl[hf * 2], kfl[hf * 2 + 1]);
                    mma16816(accS[nt], ql[ks], kfh[hf * 2], kfh[hf * 2 + 1]);
                }
            }
        }

        if (j0 == r0) {
            #pragma unroll
            for (int nt = 0; nt < 8; nt++)
                #pragma unroll
                for (int i = 0; i < 4; i++) {
                    const int col = nt * 8 + qc * 2 + (i & 1);
                    const int rr = w * 16 + qr + (i >> 1) * 8;
                    if (col > rr) accS[nt][i] = -1e30f;
                }
        }

        float corr[2];
        #pragma unroll
        for (int hrow = 0; hrow < 2; hrow++) {
            float mx = -1e30f;
            #pragma unroll
            for (int nt = 0; nt < 8; nt++) {
                mx = fmaxf(mx, fmaxf(accS[nt][hrow * 2], accS[nt][hrow * 2 + 1]));
            }
            mx = fmaxf(mx, __shfl_xor_sync(0xffffffffu, mx, 1));
            mx = fmaxf(mx, __shfl_xor_sync(0xffffffffu, mx, 2));
            const float m_new = fmaxf(mrow[hrow], mx);
            corr[hrow] = __expf(mrow[hrow] - m_new);
            mrow[hrow] = m_new;
            float rs = 0.f;
            #pragma unroll
            for (int nt = 0; nt < 8; nt++) {
                float p0 = __expf(accS[nt][hrow * 2]     - m_new);
                float p1 = __expf(accS[nt][hrow * 2 + 1] - m_new);
                accS[nt][hrow * 2]     = p0;
                accS[nt][hrow * 2 + 1] = p1;
                rs += p0 + p1;
            }
            rs += __shfl_xor_sync(0xffffffffu, rs, 1);
            rs += __shfl_xor_sync(0xffffffffu, rs, 2);
            lrow[hrow] = lrow[hrow] * corr[hrow] + rs;
        }
        #pragma unroll
        for (int nt = 0; nt < 8; nt++) {
            accO[nt][0] *= corr[0]; accO[nt][1] *= corr[0];
            accO[nt][2] *= corr[1]; accO[nt][3] *= corr[1];
        }

        #pragma unroll
        for (int ks = 0; ks < 4; ks++) {
            uint32_t pfh[4], pfl[4];
            #pragma unroll
            for (int half = 0; half < 2; half++) {
                const int nt = ks * 2 + half;
                #pragma unroll
                for (int rh = 0; rh < 2; rh++) {
                    float v0 = accS[nt][rh * 2], v1 = accS[nt][rh * 2 + 1];
                    float h0 = __bfloat162float(__float2bfloat16(v0));
                    float h1 = __bfloat162float(__float2bfloat16(v1));
                    pfh[half * 2 + rh] = packbf(h0, h1);
                    pfl[half * 2 + rh] = packbf(v0 - h0, v1 - h1);
                }
            }
            #pragma unroll
            for (int np = 0; np < 4; np++) {
                uint32_t vfh[4], vfl[4];
                const uint32_t va = (vrow + ks * 16) * QSTR + np * 32 + vcol;
                ldsm4t(vfh, uVh + va);
                ldsm4t(vfl, uVl + va);
                #pragma unroll
                for (int hf = 0; hf < 2; hf++) {
                    const int nt = np * 2 + hf;
                    mma16816(accO[nt], pfh, vfh[hf * 2], vfh[hf * 2 + 1]);
                    mma16816(accO[nt], pfh, vfl[hf * 2], vfl[hf * 2 + 1]);
                    mma16816(accO[nt], pfl, vfh[hf * 2], vfh[hf * 2 + 1]);
                }
            }
        }
    }

    const float inv0 = 1.f / lrow[0];
    const float inv1 = 1.f / lrow[1];
    const int b = bh >> 4, hh = bh & 15;
    #pragma unroll
    for (int nt = 0; nt < 8; nt++) {
        const int d = hh * 64 + nt * 8 + qc * 2;
        #pragma unroll
        for (int rh = 0; rh < 2; rh++) {
            const float inv = rh ? inv1 : inv0;
            const int row = r0 + w * 16 + qr + rh * 8;
            const size_t idx = (size_t)(b * T_ + row) * C_ + d;
            float v0 = accO[nt][rh * 2] * inv;
            float v1 = accO[nt][rh * 2 + 1] * inv;
            float h0 = __bfloat162float(__float2bfloat16(v0));
            float h1 = __bfloat162float(__float2bfloat16(v1));
            *(uint32_t*)&g_ahi[idx] = packbf(h0, h1);
            *(uint32_t*)&g_alo[idx] = packbf(v0 - h0, v1 - h1);
        }
    }
}

// ---------------------------------------------------------------------------
extern "C" void kernel_launch(void* const* d_in, const int* in_sizes, int n_in,
                              void* d_out, int out_size)
{
    const float* x  = (const float*)d_in[0];
    const float* Wq = (const float*)d_in[1];
    const float* Wk = (const float*)d_in[2];
    const float* Wv = (const float*)d_in[3];
    const float* Wo = (const float*)d_in[4];
    const float* bo = (const float*)d_in[5];
    float* out = (float*)d_out;

    __nv_bfloat16 *xhi, *xlo, *wohi, *wolo;
    cudaGetSymbolAddress((void**)&xhi,  g_xhi);
    cudaGetSymbolAddress((void**)&xlo,  g_xlo);
    cudaGetSymbolAddress((void**)&wohi, g_wohi);
    cudaGetSymbolAddress((void**)&wolo, g_wolo);

    cudaFuncSetAttribute(qkv_mma_kernel,
        cudaFuncAttributeMaxDynamicSharedMemorySize, GSMEM);
    cudaFuncSetAttribute(proj_mma_kernel,
        cudaFuncAttributeMaxDynamicSharedMemorySize, GSMEM);

    split_kernel<<<(B_ * T_ * C_ / 4 + 255) / 256, 256>>>(x, xhi, xlo, B_ * T_ * C_ / 4);
    split_wqkv_kernel<<<dim3(HS_ * C_ / 256, 48), 256>>>(Wq, Wk, Wv);
    split_kernel<<<(C_ * C_ / 4 + 255) / 256, 256>>>(Wo, wohi, wolo, C_ * C_ / 4);

    qkv_mma_kernel<<<dim3(B_ * T_ / 128, 3 * C_ / 128), 256, GSMEM>>>();

    attn_hmma_kernel<<<dim3(T_ / 64, B_ * H_), 128>>>();

    proj_mma_kernel<<<dim3(B_ * T_ / 128, C_ / 128), 256, GSMEM>>>(bo, out);
}

// round 8
// speedup vs baseline: 1.1687x; 1.1687x over previous
#include <cuda_runtime.h>
#include <cuda_bf16.h>
#include <cstdint>

#define B_  4
#define T_  2048
#define C_  1024
#define H_  16
#define HS_ 64

// ---------------------------------------------------------------------------
// Scratch (allocation-free rule: __device__ globals)
// ---------------------------------------------------------------------------
__device__ __nv_bfloat16 g_xhi[B_ * T_ * C_];
__device__ __nv_bfloat16 g_xlo[B_ * T_ * C_];
__device__ __nv_bfloat16 g_wthi[3 * H_ * HS_ * C_];   // [n=z*64+d][c] K-major
__device__ __nv_bfloat16 g_wtlo[3 * H_ * HS_ * C_];
__device__ __nv_bfloat16 g_wohi[C_ * C_];             // [n][k]
__device__ __nv_bfloat16 g_wolo[C_ * C_];
__device__ __nv_bfloat16 g_ahi[B_ * T_ * C_];
__device__ __nv_bfloat16 g_alo[B_ * T_ * C_];

// q/k/v in bf16 hi/lo, layout [bh][t][64]; q pre-scaled by 1/sqrt(HS)
__device__ __nv_bfloat16 g_qh[B_ * H_ * T_ * HS_];
__device__ __nv_bfloat16 g_ql[B_ * H_ * T_ * HS_];
__device__ __nv_bfloat16 g_kh[B_ * H_ * T_ * HS_];
__device__ __nv_bfloat16 g_kl[B_ * H_ * T_ * HS_];
__device__ __nv_bfloat16 g_vh[B_ * H_ * T_ * HS_];
__device__ __nv_bfloat16 g_vl[B_ * H_ * T_ * HS_];

// ---------------------------------------------------------------------------
// Portable tensor-core primitives (sm_80+ ISA; compiles at base compute_103)
// ---------------------------------------------------------------------------
__device__ __forceinline__ uint32_t smem_u32(const void* p) {
    uint32_t a;
    asm("{ .reg .u64 t; cvta.to.shared.u64 t, %1; cvt.u32.u64 %0, t; }"
        : "=r"(a) : "l"(p));
    return a;
}

__device__ __forceinline__ void ldsm4(uint32_t* r, uint32_t addr) {
    asm volatile("ldmatrix.sync.aligned.m8n8.x4.shared.b16 {%0,%1,%2,%3}, [%4];"
        : "=r"(r[0]), "=r"(r[1]), "=r"(r[2]), "=r"(r[3]) : "r"(addr));
}

__device__ __forceinline__ void ldsm4t(uint32_t* r, uint32_t addr) {
    asm volatile("ldmatrix.sync.aligned.m8n8.x4.trans.shared.b16 {%0,%1,%2,%3}, [%4];"
        : "=r"(r[0]), "=r"(r[1]), "=r"(r[2]), "=r"(r[3]) : "r"(addr));
}

__device__ __forceinline__ void mma16816(float* c, const uint32_t* a,
                                         const uint32_t b0, const uint32_t b1) {
    asm volatile(
        "mma.sync.aligned.m16n8k16.row.col.f32.bf16.bf16.f32 "
        "{%0,%1,%2,%3}, {%4,%5,%6,%7}, {%8,%9}, {%0,%1,%2,%3};"
        : "+f"(c[0]), "+f"(c[1]), "+f"(c[2]), "+f"(c[3])
        : "r"(a[0]), "r"(a[1]), "r"(a[2]), "r"(a[3]), "r"(b0), "r"(b1));
}

__device__ __forceinline__ uint32_t packbf(float a, float b) {
    __nv_bfloat162 t = __floats2bfloat162_rn(a, b);
    return *(uint32_t*)&t;
}

__device__ __forceinline__ void cp16(uint32_t dst, const void* src) {
    asm volatile("cp.async.cg.shared.global [%0], [%1], 16;"
        :: "r"(dst), "l"(src) : "memory");
}
#define CP_COMMIT() asm volatile("cp.async.commit_group;" ::: "memory")
#define CP_WAIT(n)  asm volatile("cp.async.wait_group %0;" :: "n"(n) : "memory")

// ---------------------------------------------------------------------------
// fp32 -> bf16 hi/lo split kernels
// ---------------------------------------------------------------------------
struct __align__(8) bf4 { __nv_bfloat16 a, b, c, d; };

__device__ __forceinline__ void split4(float4 v, bf4& hv, bf4& lv) {
    __nv_bfloat16 h0 = __float2bfloat16(v.x);
    __nv_bfloat16 h1 = __float2bfloat16(v.y);
    __nv_bfloat16 h2 = __float2bfloat16(v.z);
    __nv_bfloat16 h3 = __float2bfloat16(v.w);
    hv = {h0, h1, h2, h3};
    lv = {__float2bfloat16(v.x - __bfloat162float(h0)),
          __float2bfloat16(v.y - __bfloat162float(h1)),
          __float2bfloat16(v.z - __bfloat162float(h2)),
          __float2bfloat16(v.w - __bfloat162float(h3))};
}

__global__ __launch_bounds__(256) void split_kernel(
    const float* __restrict__ in,
    __nv_bfloat16* __restrict__ hi,
    __nv_bfloat16* __restrict__ lo, int n4)
{
    int i = blockIdx.x * blockDim.x + threadIdx.x;
    if (i >= n4) return;
    bf4 hv, lv;
    split4(((const float4*)in)[i], hv, lv);
    ((bf4*)hi)[i] = hv;
    ((bf4*)lo)[i] = lv;
}

// W[h][c][d] (fp32) -> Wt[z][d][c] (bf16 hi/lo), z = p*16+h
__global__ __launch_bounds__(256) void split_wqkv_kernel(
    const float* __restrict__ Wq,
    const float* __restrict__ Wk,
    const float* __restrict__ Wv)
{
    int z = blockIdx.y;
    int p = z >> 4, h = z & 15;
    const float* W = (p == 0 ? Wq : (p == 1 ? Wk : Wv)) + (size_t)h * C_ * HS_;
    int idx = blockIdx.x * blockDim.x + threadIdx.x;
    int d = idx & 63;
    int c = idx >> 6;
    float v = W[(size_t)c * HS_ + d];
    __nv_bfloat16 hv = __float2bfloat16(v);
    __nv_bfloat16 lv = __float2bfloat16(v - __bfloat162float(hv));
    size_t o = ((size_t)z * HS_ + d) * C_ + c;
    g_wthi[o] = hv;
    g_wtlo[o] = lv;
}

// ---------------------------------------------------------------------------
// Pipelined HMMA GEMM: CTA 128x128, warp tile 64x32 (8 warps, 2x4), BK=32,
// 2-stage cp.async double buffering. A,B K-major bf16 hi/lo.
// ---------------------------------------------------------------------------
#define GSTR    80
#define OFF_AH  0
#define OFF_AL  10240
#define OFF_BH  20480
#define OFF_BL  30720
#define STG_SZ  40960
#define GSMEM   (2 * STG_SZ)   // 81920

__device__ __forceinline__ void stage_load(
    uint32_t sbase,
    const __nv_bfloat16* __restrict__ Ah, const __nv_bfloat16* __restrict__ Al,
    const __nv_bfloat16* __restrict__ Bh, const __nv_bfloat16* __restrict__ Bl,
    int a_row0, int b_row0, int k0, int t)
{
    const int row = t >> 1;
    const int cb  = (t & 1) * 32;            // byte offset within 64B row
    const uint32_t so = (uint32_t)row * GSTR + cb;
    const size_t ga = (size_t)(a_row0 + row) * C_ + k0 + (cb >> 1);
    const size_t gb = (size_t)(b_row0 + row) * C_ + k0 + (cb >> 1);
    cp16(sbase + OFF_AH + so,      Ah + ga);
    cp16(sbase + OFF_AH + so + 16, Ah + ga + 8);
    cp16(sbase + OFF_AL + so,      Al + ga);
    cp16(sbase + OFF_AL + so + 16, Al + ga + 8);
    cp16(sbase + OFF_BH + so,      Bh + gb);
    cp16(sbase + OFF_BH + so + 16, Bh + gb + 8);
    cp16(sbase + OFF_BL + so,      Bl + gb);
    cp16(sbase + OFF_BL + so + 16, Bl + gb + 8);
}

__device__ __forceinline__ void stage_compute(
    uint32_t sbase, const uint32_t aoff[4], const uint32_t boff[2],
    float acc[4][4][4])
{
    #pragma unroll
    for (int kk = 0; kk < 2; kk++) {
        const uint32_t kb = (uint32_t)kk * 32;
        uint32_t ah[4][4], al[4][4];
        #pragma unroll
        for (int mt = 0; mt < 4; mt++) {
            ldsm4(ah[mt], sbase + OFF_AH + aoff[mt] + kb);
            ldsm4(al[mt], sbase + OFF_AL + aoff[mt] + kb);
        }
        #pragma unroll
        for (int np = 0; np < 2; np++) {
            uint32_t bh[4], bl[4];
            ldsm4(bh, sbase + OFF_BH + boff[np] + kb);
            ldsm4(bl, sbase + OFF_BL + boff[np] + kb);
            #pragma unroll
            for (int mt = 0; mt < 4; mt++)
                #pragma unroll
                for (int hf = 0; hf < 2; hf++) {
                    const int nt = np * 2 + hf;
                    mma16816(acc[mt][nt], ah[mt], bh[hf * 2], bh[hf * 2 + 1]);
                    mma16816(acc[mt][nt], ah[mt], bl[hf * 2], bl[hf * 2 + 1]);
                    mma16816(acc[mt][nt], al[mt], bh[hf * 2], bh[hf * 2 + 1]);
                }
        }
    }
}

__device__ __forceinline__ void gemm_mainloop(
    const __nv_bfloat16* __restrict__ Ah, const __nv_bfloat16* __restrict__ Al,
    const __nv_bfloat16* __restrict__ Bh, const __nv_bfloat16* __restrict__ Bl,
    int a_row0, int b_row0, uint32_t sb, float acc[4][4][4])
{
    const int t = threadIdx.x;
    const int wid = t >> 5, lane = t & 31;
    const int warp_m = wid & 1, warp_n = wid >> 1;
    const int g = lane >> 3, lr = lane & 7;

    uint32_t aoff[4], boff[2];
    #pragma unroll
    for (int mt = 0; mt < 4; mt++)
        aoff[mt] = (uint32_t)(warp_m * 64 + mt * 16 + (g & 1) * 8 + lr) * GSTR
                 + (uint32_t)(g >> 1) * 16;
    #pragma unroll
    for (int np = 0; np < 2; np++)
        boff[np] = (uint32_t)(warp_n * 32 + np * 16 + (g >> 1) * 8 + lr) * GSTR
                 + (uint32_t)(g & 1) * 16;

    #pragma unroll
    for (int mt = 0; mt < 4; mt++)
        #pragma unroll
        for (int nt = 0; nt < 4; nt++)
            #pragma unroll
            for (int i = 0; i < 4; i++) acc[mt][nt][i] = 0.f;

    const int NCH = C_ / 32;   // 32 chunks
    stage_load(sb, Ah, Al, Bh, Bl, a_row0, b_row0, 0, t);
    CP_COMMIT();
    for (int i = 0; i < NCH; i++) {
        const uint32_t scur = sb + (uint32_t)(i & 1) * STG_SZ;
        if (i + 1 < NCH) {
            stage_load(sb + (uint32_t)((i + 1) & 1) * STG_SZ,
                       Ah, Al, Bh, Bl, a_row0, b_row0, (i + 1) * 32, t);
            CP_COMMIT();
            CP_WAIT(1);
        } else {
            CP_WAIT(0);
        }
        __syncthreads();
        stage_compute(scur, aoff, boff, acc);
        __syncthreads();
    }
}

// Fused QKV GEMM: [8192,1024] @ [1024,3072]; grid (64, 24), block 256.
__global__ __launch_bounds__(256, 2) void qkv_mma_kernel()
{
    extern __shared__ __align__(16) unsigned char dynsmem[];
    const uint32_t sb = smem_u32(dynsmem);
    const int m0 = blockIdx.x * 128;
    const int n0 = blockIdx.y * 128;

    float acc[4][4][4];
    gemm_mainloop(g_xhi, g_xlo, g_wthi, g_wtlo, m0, n0, sb, acc);

    const int wid = threadIdx.x >> 5, lane = threadIdx.x & 31;
    const int warp_m = wid & 1, warp_n = wid >> 1;
    const int qr = lane >> 2, qc2 = (lane & 3) * 2;

    #pragma unroll
    for (int nt = 0; nt < 4; nt++) {
        const int gn = n0 + warp_n * 32 + nt * 8 + qc2;
        const int z = gn >> 6, d = gn & 63;
        const int p = z >> 4, h = z & 15;
        __nv_bfloat16* outh = (p == 0 ? g_qh : (p == 1 ? g_kh : g_vh));
        __nv_bfloat16* outl = (p == 0 ? g_ql : (p == 1 ? g_kl : g_vl));
        const float scale = (p == 0) ? 0.125f : 1.0f;
        #pragma unroll
        for (int mt = 0; mt < 4; mt++) {
            #pragma unroll
            for (int rh = 0; rh < 2; rh++) {
                const int gm = m0 + warp_m * 64 + mt * 16 + qr + rh * 8;
                const int b = gm >> 11, tt = gm & (T_ - 1);
                const size_t idx = ((size_t)(b * H_ + h) * T_ + tt) * HS_ + d;
                float v0 = acc[mt][nt][rh * 2] * scale;
                float v1 = acc[mt][nt][rh * 2 + 1] * scale;
                float h0 = __bfloat162float(__float2bfloat16(v0));
                float h1 = __bfloat162float(__float2bfloat16(v1));
                *(uint32_t*)&outh[idx] = packbf(h0, h1);
                *(uint32_t*)&outl[idx] = packbf(v0 - h0, v1 - h1);
            }
        }
    }
}

// Output projection: [8192,1024] @ [1024,1024]; grid (64, 8), block 256.
__global__ __launch_bounds__(256, 2) void proj_mma_kernel(
    const float* __restrict__ bo, float* __restrict__ out)
{
    extern __shared__ __align__(16) unsigned char dynsmem[];
    const uint32_t sb = smem_u32(dynsmem);
    const int m0 = blockIdx.x * 128;
    const int n0 = blockIdx.y * 128;

    float acc[4][4][4];
    gemm_mainloop(g_ahi, g_alo, g_wohi, g_wolo, m0, n0, sb, acc);

    const int wid = threadIdx.x >> 5, lane = threadIdx.x & 31;
    const int warp_m = wid & 1, warp_n = wid >> 1;
    const int qr = lane >> 2, qc2 = (lane & 3) * 2;

    #pragma unroll
    for (int nt = 0; nt < 4; nt++) {
        const int gn = n0 + warp_n * 32 + nt * 8 + qc2;
        const float2 bb = *(const float2*)&bo[gn];
        #pragma unroll
        for (int mt = 0; mt < 4; mt++) {
            #pragma unroll
            for (int rh = 0; rh < 2; rh++) {
                const int gm = m0 + warp_m * 64 + mt * 16 + qr + rh * 8;
                *(float2*)(out + (size_t)gm * C_ + gn) =
                    make_float2(acc[mt][nt][rh * 2] + bb.x,
                                acc[mt][nt][rh * 2 + 1] + bb.y);
            }
        }
    }
}

// ---------------------------------------------------------------------------
// HMMA causal flash attention with cp.async double-buffered K/V stages.
// CTA: 64 q-rows x one bh, 4 warps. Smem: Qh,Ql + 2 stages of {Kh,Kl,Vh,Vl}.
// ---------------------------------------------------------------------------
#define QSTR 144
#define AQ_   (64 * QSTR)        // 9216 per buffer
#define AKV_STG (4 * AQ_)        // 36864 per stage
#define ASMEM (2 * AQ_ + 2 * AKV_STG)   // 92160

__device__ __forceinline__ void attn_stage_kv(uint32_t st, size_t base,
                                              int j0, int t)
{
    const int crow = t >> 1;
    const int coff = (t & 1) * 64;   // bytes
    const uint32_t doff = (uint32_t)crow * QSTR + coff;
    const __nv_bfloat16* pkh = g_kh + base + (size_t)(j0 + crow) * HS_ + (coff >> 1);
    const __nv_bfloat16* pkl = g_kl + base + (size_t)(j0 + crow) * HS_ + (coff >> 1);
    const __nv_bfloat16* pvh = g_vh + base + (size_t)(j0 + crow) * HS_ + (coff >> 1);
    const __nv_bfloat16* pvl = g_vl + base + (size_t)(j0 + crow) * HS_ + (coff >> 1);
    #pragma unroll
    for (int j = 0; j < 4; j++) {
        cp16(st + 0 * AQ_ + doff + j * 16, pkh + j * 8);
        cp16(st + 1 * AQ_ + doff + j * 16, pkl + j * 8);
        cp16(st + 2 * AQ_ + doff + j * 16, pvh + j * 8);
        cp16(st + 3 * AQ_ + doff + j * 16, pvl + j * 8);
    }
}

__global__ __launch_bounds__(128) void attn_hmma_kernel()
{
    extern __shared__ __align__(16) unsigned char dynsmem[];
    const uint32_t sb = smem_u32(dynsmem);
    const uint32_t uQh = sb, uQl = sb + AQ_;
    unsigned char* sQh = dynsmem;
    unsigned char* sQl = dynsmem + AQ_;

    const int bh = blockIdx.y;
    const int r0 = blockIdx.x * 64;
    const int t  = threadIdx.x;
    const int w  = t >> 5, lane = t & 31;
    const int g = lane >> 3, lr = lane & 7;
    const int qr = lane >> 2, qc = lane & 3;

    const size_t base = (size_t)bh * T_ * HS_;

    const int crow = t >> 1;
    const int coff = (t & 1) * 64;

    // ---- prefetch KV tile 0 (stage 0)
    attn_stage_kv(sb + 2 * AQ_, base, 0, t);
    CP_COMMIT();

    // ---- prologue: Q tile -> smem -> fragments
    {
        const unsigned char* gh =
            (const unsigned char*)(g_qh + base + (size_t)(r0 + crow) * HS_) + coff;
        const unsigned char* gl =
            (const unsigned char*)(g_ql + base + (size_t)(r0 + crow) * HS_) + coff;
        uint4 a0 = ((const uint4*)gh)[0], a1 = ((const uint4*)gh)[1];
        uint4 a2 = ((const uint4*)gh)[2], a3 = ((const uint4*)gh)[3];
        uint4 b0 = ((const uint4*)gl)[0], b1 = ((const uint4*)gl)[1];
        uint4 b2 = ((const uint4*)gl)[2], b3 = ((const uint4*)gl)[3];
        uint4* dh = (uint4*)(sQh + crow * QSTR + coff);
        uint4* dl = (uint4*)(sQl + crow * QSTR + coff);
        dh[0] = a0; dh[1] = a1; dh[2] = a2; dh[3] = a3;
        dl[0] = b0; dl[1] = b1; dl[2] = b2; dl[3] = b3;
    }
    __syncthreads();

    uint32_t qh[4][4], ql[4][4];
    {
        const uint32_t qoff = (uint32_t)(w * 16 + (g & 1) * 8 + lr) * QSTR
                            + (uint32_t)((g >> 1) * 8) * 2;
        #pragma unroll
        for (int ks = 0; ks < 4; ks++) {
            ldsm4(qh[ks], uQh + qoff + ks * 32);
            ldsm4(ql[ks], uQl + qoff + ks * 32);
        }
    }

    float accO[8][4];
    #pragma unroll
    for (int nt = 0; nt < 8; nt++)
        #pragma unroll
        for (int i = 0; i < 4; i++) accO[nt][i] = 0.f;
    float mrow[2] = {-1e30f, -1e30f};
    float lrow[2] = {0.f, 0.f};

    uint32_t koff[4];
    #pragma unroll
    for (int np = 0; np < 4; np++)
        koff[np] = (uint32_t)(np * 16 + (g >> 1) * 8 + lr) * QSTR
                 + (uint32_t)((g & 1) * 8) * 2;
    const uint32_t vrow = (uint32_t)((g & 1) * 8 + lr);
    const uint32_t vcol = (uint32_t)((g >> 1) * 8) * 2;

    const int ntiles = (r0 >> 6) + 1;
    for (int i = 0; i < ntiles; i++) {
        CP_WAIT(0);
        __syncthreads();
        if (i + 1 < ntiles) {
            attn_stage_kv(sb + 2 * AQ_ + (uint32_t)((i + 1) & 1) * AKV_STG,
                          base, (i + 1) * 64, t);
            CP_COMMIT();
        }
        const uint32_t st = sb + 2 * AQ_ + (uint32_t)(i & 1) * AKV_STG;
        const uint32_t uKh = st, uKl = st + AQ_;
        const uint32_t uVh = st + 2 * AQ_, uVl = st + 3 * AQ_;
        const int j0 = i * 64;

        float accS[8][4];
        #pragma unroll
        for (int nt = 0; nt < 8; nt++)
            #pragma unroll
            for (int ii = 0; ii < 4; ii++) accS[nt][ii] = 0.f;

        #pragma unroll
        for (int ks = 0; ks < 4; ks++) {
            #pragma unroll
            for (int np = 0; np < 4; np++) {
                uint32_t kfh[4], kfl[4];
                ldsm4(kfh, uKh + koff[np] + ks * 32);
                ldsm4(kfl, uKl + koff[np] + ks * 32);
                #pragma unroll
                for (int hf = 0; hf < 2; hf++) {
                    const int nt = np * 2 + hf;
                    mma16816(accS[nt], qh[ks], kfh[hf * 2], kfh[hf * 2 + 1]);
                    mma16816(accS[nt], qh[ks], kfl[hf * 2], kfl[hf * 2 + 1]);
                    mma16816(accS[nt], ql[ks], kfh[hf * 2], kfh[hf * 2 + 1]);
                }
            }
        }

        if (j0 == r0) {
            #pragma unroll
            for (int nt = 0; nt < 8; nt++)
                #pragma unroll
                for (int ii = 0; ii < 4; ii++) {
                    const int col = nt * 8 + qc * 2 + (ii & 1);
                    const int rr = w * 16 + qr + (ii >> 1) * 8;
                    if (col > rr) accS[nt][ii] = -1e30f;
                }
        }

        float corr[2];
        #pragma unroll
        for (int hrow = 0; hrow < 2; hrow++) {
            float mx = -1e30f;
            #pragma unroll
            for (int nt = 0; nt < 8; nt++) {
                mx = fmaxf(mx, fmaxf(accS[nt][hrow * 2], accS[nt][hrow * 2 + 1]));
            }
            mx = fmaxf(mx, __shfl_xor_sync(0xffffffffu, mx, 1));
            mx = fmaxf(mx, __shfl_xor_sync(0xffffffffu, mx, 2));
            const float m_new = fmaxf(mrow[hrow], mx);
            corr[hrow] = __expf(mrow[hrow] - m_new);
            mrow[hrow] = m_new;
            float rs = 0.f;
            #pragma unroll
            for (int nt = 0; nt < 8; nt++) {
                float p0 = __expf(accS[nt][hrow * 2]     - m_new);
                float p1 = __expf(accS[nt][hrow * 2 + 1] - m_new);
                accS[nt][hrow * 2]     = p0;
                accS[nt][hrow * 2 + 1] = p1;
                rs += p0 + p1;
            }
            rs += __shfl_xor_sync(0xffffffffu, rs, 1);
            rs += __shfl_xor_sync(0xffffffffu, rs, 2);
            lrow[hrow] = lrow[hrow] * corr[hrow] + rs;
        }
        #pragma unroll
        for (int nt = 0; nt < 8; nt++) {
            accO[nt][0] *= corr[0]; accO[nt][1] *= corr[0];
            accO[nt][2] *= corr[1]; accO[nt][3] *= corr[1];
        }

        #pragma unroll
        for (int ks = 0; ks < 4; ks++) {
            uint32_t pfh[4], pfl[4];
            #pragma unroll
            for (int half = 0; half < 2; half++) {
                const int nt = ks * 2 + half;
                #pragma unroll
                for (int rh = 0; rh < 2; rh++) {
                    float v0 = accS[nt][rh * 2], v1 = accS[nt][rh * 2 + 1];
                    float h0 = __bfloat162float(__float2bfloat16(v0));
                    float h1 = __bfloat162float(__float2bfloat16(v1));
                    pfh[half * 2 + rh] = packbf(h0, h1);
                    pfl[half * 2 + rh] = packbf(v0 - h0, v1 - h1);
                }
            }
            #pragma unroll
            for (int np = 0; np < 4; np++) {
                uint32_t vfh[4], vfl[4];
                const uint32_t va = (vrow + ks * 16) * QSTR + np * 32 + vcol;
                ldsm4t(vfh, uVh + va);
                ldsm4t(vfl, uVl + va);
                #pragma unroll
                for (int hf = 0; hf < 2; hf++) {
                    const int nt = np * 2 + hf;
                    mma16816(accO[nt], pfh, vfh[hf * 2], vfh[hf * 2 + 1]);
                    mma16816(accO[nt], pfh, vfl[hf * 2], vfl[hf * 2 + 1]);
                    mma16816(accO[nt], pfl, vfh[hf * 2], vfh[hf * 2 + 1]);
                }
            }
        }
        __syncthreads();
    }

    const float inv0 = 1.f / lrow[0];
    const float inv1 = 1.f / lrow[1];
    const int b = bh >> 4, hh = bh & 15;
    #pragma unroll
    for (int nt = 0; nt < 8; nt++) {
        const int d = hh * 64 + nt * 8 + qc * 2;
        #pragma unroll
        for (int rh = 0; rh < 2; rh++) {
            const float inv = rh ? inv1 : inv0;
            const int row = r0 + w * 16 + qr + rh * 8;
            const size_t idx = (size_t)(b * T_ + row) * C_ + d;
            float v0 = accO[nt][rh * 2] * inv;
            float v1 = accO[nt][rh * 2 + 1] * inv;
            float h0 = __bfloat162float(__float2bfloat16(v0));
            float h1 = __bfloat162float(__float2bfloat16(v1));
            *(uint32_t*)&g_ahi[idx] = packbf(h0, h1);
            *(uint32_t*)&g_alo[idx] = packbf(v0 - h0, v1 - h1);
        }
    }
}

// ---------------------------------------------------------------------------
extern "C" void kernel_launch(void* const* d_in, const int* in_sizes, int n_in,
                              void* d_out, int out_size)
{
    const float* x  = (const float*)d_in[0];
    const float* Wq = (const float*)d_in[1];
    const float* Wk = (const float*)d_in[2];
    const float* Wv = (const float*)d_in[3];
    const float* Wo = (const float*)d_in[4];
    const float* bo = (const float*)d_in[5];
    float* out = (float*)d_out;

    __nv_bfloat16 *xhi, *xlo, *wohi, *wolo;
    cudaGetSymbolAddress((void**)&xhi,  g_xhi);
    cudaGetSymbolAddress((void**)&xlo,  g_xlo);
    cudaGetSymbolAddress((void**)&wohi, g_wohi);
    cudaGetSymbolAddress((void**)&wolo, g_wolo);

    cudaFuncSetAttribute(qkv_mma_kernel,
        cudaFuncAttributeMaxDynamicSharedMemorySize, GSMEM);
    cudaFuncSetAttribute(proj_mma_kernel,
        cudaFuncAttributeMaxDynamicSharedMemorySize, GSMEM);
    cudaFuncSetAttribute(attn_hmma_kernel,
        cudaFuncAttributeMaxDynamicSharedMemorySize, ASMEM);

    split_kernel<<<(B_ * T_ * C_ / 4 + 255) / 256, 256>>>(x, xhi, xlo, B_ * T_ * C_ / 4);
    split_wqkv_kernel<<<dim3(HS_ * C_ / 256, 48), 256>>>(Wq, Wk, Wv);
    split_kernel<<<(C_ * C_ / 4 + 255) / 256, 256>>>(Wo, wohi, wolo, C_ * C_ / 4);

    qkv_mma_kernel<<<dim3(B_ * T_ / 128, 3 * C_ / 128), 256, GSMEM>>>();

    attn_hmma_kernel<<<dim3(T_ / 64, B_ * H_), 128, ASMEM>>>();

    proj_mma_kernel<<<dim3(B_ * T_ / 128, C_ / 128), 256, GSMEM>>>(bo, out);
}

// round 11
// speedup vs baseline: 1.2540x; 1.0730x over previous
#include <cuda_runtime.h>
#include <cuda_bf16.h>
#include <cstdint>

#define B_  4
#define T_  2048
#define C_  1024
#define H_  16
#define HS_ 64

// ---------------------------------------------------------------------------
// Scratch (allocation-free rule: __device__ globals)
// ---------------------------------------------------------------------------
__device__ __nv_bfloat16 g_xhi[B_ * T_ * C_];
__device__ __nv_bfloat16 g_xlo[B_ * T_ * C_];
__device__ __nv_bfloat16 g_wthi[3 * H_ * HS_ * C_];   // [n=z*64+d][c] K-major
__device__ __nv_bfloat16 g_wtlo[3 * H_ * HS_ * C_];
__device__ __nv_bfloat16 g_wohi[C_ * C_];             // [n][k]
__device__ __nv_bfloat16 g_wolo[C_ * C_];
__device__ __nv_bfloat16 g_ahi[B_ * T_ * C_];
__device__ __nv_bfloat16 g_alo[B_ * T_ * C_];

// q/k/v in bf16 hi/lo, layout [bh][t][64]; q pre-scaled by log2e/sqrt(HS)
__device__ __nv_bfloat16 g_qh[B_ * H_ * T_ * HS_];
__device__ __nv_bfloat16 g_ql[B_ * H_ * T_ * HS_];
__device__ __nv_bfloat16 g_kh[B_ * H_ * T_ * HS_];
__device__ __nv_bfloat16 g_kl[B_ * H_ * T_ * HS_];
__device__ __nv_bfloat16 g_vh[B_ * H_ * T_ * HS_];
__device__ __nv_bfloat16 g_vl[B_ * H_ * T_ * HS_];

// ---------------------------------------------------------------------------
// Portable tensor-core primitives (sm_80+ ISA; compiles at base compute_103)
// ---------------------------------------------------------------------------
__device__ __forceinline__ uint32_t smem_u32(const void* p) {
    uint32_t a;
    asm("{ .reg .u64 t; cvta.to.shared.u64 t, %1; cvt.u32.u64 %0, t; }"
        : "=r"(a) : "l"(p));
    return a;
}

__device__ __forceinline__ void ldsm4(uint32_t* r, uint32_t addr) {
    asm volatile("ldmatrix.sync.aligned.m8n8.x4.shared.b16 {%0,%1,%2,%3}, [%4];"
        : "=r"(r[0]), "=r"(r[1]), "=r"(r[2]), "=r"(r[3]) : "r"(addr));
}

__device__ __forceinline__ void ldsm4t(uint32_t* r, uint32_t addr) {
    asm volatile("ldmatrix.sync.aligned.m8n8.x4.trans.shared.b16 {%0,%1,%2,%3}, [%4];"
        : "=r"(r[0]), "=r"(r[1]), "=r"(r[2]), "=r"(r[3]) : "r"(addr));
}

__device__ __forceinline__ void mma16816(float* c, const uint32_t* a,
                                         const uint32_t b0, const uint32_t b1) {
    asm volatile(
        "mma.sync.aligned.m16n8k16.row.col.f32.bf16.bf16.f32 "
        "{%0,%1,%2,%3}, {%4,%5,%6,%7}, {%8,%9}, {%0,%1,%2,%3};"
        : "+f"(c[0]), "+f"(c[1]), "+f"(c[2]), "+f"(c[3])
        : "r"(a[0]), "r"(a[1]), "r"(a[2]), "r"(a[3]), "r"(b0), "r"(b1));
}

__device__ __forceinline__ uint32_t packbf(float a, float b) {
    __nv_bfloat162 t = __floats2bfloat162_rn(a, b);
    return *(uint32_t*)&t;
}

__device__ __forceinline__ float ex2(float x) {
    float r;
    asm("ex2.approx.ftz.f32 %0, %1;" : "=f"(r) : "f"(x));
    return r;
}

__device__ __forceinline__ void cp16(uint32_t dst, const void* src) {
    asm volatile("cp.async.cg.shared.global [%0], [%1], 16;"
        :: "r"(dst), "l"(src) : "memory");
}
#define CP_COMMIT() asm volatile("cp.async.commit_group;" ::: "memory")
#define CP_WAIT(n)  asm volatile("cp.async.wait_group %0;" :: "n"(n) : "memory")

// ---------------------------------------------------------------------------
// fp32 -> bf16 hi/lo split kernels
// ---------------------------------------------------------------------------
struct __align__(8) bf4 { __nv_bfloat16 a, b, c, d; };

__device__ __forceinline__ void split4(float4 v, bf4& hv, bf4& lv) {
    __nv_bfloat16 h0 = __float2bfloat16(v.x);
    __nv_bfloat16 h1 = __float2bfloat16(v.y);
    __nv_bfloat16 h2 = __float2bfloat16(v.z);
    __nv_bfloat16 h3 = __float2bfloat16(v.w);
    hv = {h0, h1, h2, h3};
    lv = {__float2bfloat16(v.x - __bfloat162float(h0)),
          __float2bfloat16(v.y - __bfloat162float(h1)),
          __float2bfloat16(v.z - __bfloat162float(h2)),
          __float2bfloat16(v.w - __bfloat162float(h3))};
}

__global__ __launch_bounds__(256) void split_kernel(
    const float* __restrict__ in,
    __nv_bfloat16* __restrict__ hi,
    __nv_bfloat16* __restrict__ lo, int n4)
{
    int i = blockIdx.x * blockDim.x + threadIdx.x;
    if (i >= n4) return;
    bf4 hv, lv;
    split4(((const float4*)in)[i], hv, lv);
    ((bf4*)hi)[i] = hv;
    ((bf4*)lo)[i] = lv;
}

// W[h][c][d] (fp32) -> Wt[z][d][c] (bf16 hi/lo), z = p*16+h
__global__ __launch_bounds__(256) void split_wqkv_kernel(
    const float* __restrict__ Wq,
    const float* __restrict__ Wk,
    const float* __restrict__ Wv)
{
    int z = blockIdx.y;
    int p = z >> 4, h = z & 15;
    const float* W = (p == 0 ? Wq : (p == 1 ? Wk : Wv)) + (size_t)h * C_ * HS_;
    int idx = blockIdx.x * blockDim.x + threadIdx.x;
    int d = idx & 63;
    int c = idx >> 6;
    float v = W[(size_t)c * HS_ + d];
    __nv_bfloat16 hv = __float2bfloat16(v);
    __nv_bfloat16 lv = __float2bfloat16(v - __bfloat162float(hv));
    size_t o = ((size_t)z * HS_ + d) * C_ + c;
    g_wthi[o] = hv;
    g_wtlo[o] = lv;
}

// ---------------------------------------------------------------------------
// Pipelined HMMA GEMM: CTA 128x128, warp tile 64x32 (8 warps, 2x4), BK=32,
// 3-stage cp.async pipeline, XOR-swizzled smem (64B rows, conflict-free),
// ONE __syncthreads per chunk. A,B K-major bf16 hi/lo.
// Swizzle: 16B chunk index c16 (0..3) -> c16 ^ ((row>>1)&3).
// ---------------------------------------------------------------------------
#define SOFF_AH 0
#define SOFF_AL 8192
#define SOFF_BH 16384
#define SOFF_BL 24576
#define SSTG    32768
#define GSMEM   (3 * SSTG)   // 98304

__device__ __forceinline__ uint32_t swz(uint32_t row, uint32_t c16) {
    return row * 64 + (((c16 ^ (row >> 1)) & 3u) << 4);
}

__device__ __forceinline__ void stage_load(
    uint32_t sbase,
    const __nv_bfloat16* __restrict__ Ah, const __nv_bfloat16* __restrict__ Al,
    const __nv_bfloat16* __restrict__ Bh, const __nv_bfloat16* __restrict__ Bl,
    int a_row0, int b_row0, int k0, int t)
{
    const uint32_t row = (uint32_t)(t >> 1);
    const uint32_t c0  = (uint32_t)(t & 1) * 2;      // c16 base {0,2}
    const uint32_t s0 = swz(row, c0), s1 = swz(row, c0 + 1);
    const size_t ga = (size_t)(a_row0 + (int)row) * C_ + k0 + (int)c0 * 8;
    const size_t gb = (size_t)(b_row0 + (int)row) * C_ + k0 + (int)c0 * 8;
    cp16(sbase + SOFF_AH + s0, Ah + ga);
    cp16(sbase + SOFF_AH + s1, Ah + ga + 8);
    cp16(sbase + SOFF_AL + s0, Al + ga);
    cp16(sbase + SOFF_AL + s1, Al + ga + 8);
    cp16(sbase + SOFF_BH + s0, Bh + gb);
    cp16(sbase + SOFF_BH + s1, Bh + gb + 8);
    cp16(sbase + SOFF_BL + s0, Bl + gb);
    cp16(sbase + SOFF_BL + s1, Bl + gb + 8);
}

__device__ __forceinline__ void stage_compute(
    uint32_t sbase,
    const uint32_t arow64[4], const uint32_t axr[4], uint32_t ac0,
    const uint32_t brow64[2], const uint32_t bxr[2], uint32_t bc0,
    float acc[4][4][4])
{
    #pragma unroll
    for (int kk = 0; kk < 2; kk++) {
        uint32_t ah[4][4], al[4][4];
        #pragma unroll
        for (int mt = 0; mt < 4; mt++) {
            const uint32_t ca = (((ac0 + 2 * kk) ^ axr[mt]) & 3u) << 4;
            ldsm4(ah[mt], sbase + SOFF_AH + arow64[mt] + ca);
            ldsm4(al[mt], sbase + SOFF_AL + arow64[mt] + ca);
        }
        #pragma unroll
        for (int np = 0; np < 2; np++) {
            const uint32_t cb = (((bc0 + 2 * kk) ^ bxr[np]) & 3u) << 4;
            uint32_t bh[4], bl[4];
            ldsm4(bh, sbase + SOFF_BH + brow64[np] + cb);
            ldsm4(bl, sbase + SOFF_BL + brow64[np] + cb);
            #pragma unroll
            for (int mt = 0; mt < 4; mt++)
                #pragma unroll
                for (int hf = 0; hf < 2; hf++) {
                    const int nt = np * 2 + hf;
                    mma16816(acc[mt][nt], ah[mt], bh[hf * 2], bh[hf * 2 + 1]);
                    mma16816(acc[mt][nt], ah[mt], bl[hf * 2], bl[hf * 2 + 1]);
                    mma16816(acc[mt][nt], al[mt], bh[hf * 2], bh[hf * 2 + 1]);
                }
        }
    }
}

__device__ __forceinline__ void gemm_mainloop(
    const __nv_bfloat16* __restrict__ Ah, const __nv_bfloat16* __restrict__ Al,
    const __nv_bfloat16* __restrict__ Bh, const __nv_bfloat16* __restrict__ Bl,
    int a_row0, int b_row0, uint32_t sb, float acc[4][4][4])
{
    const int t = threadIdx.x;
    const int wid = t >> 5, lane = t & 31;
    const int warp_m = wid & 1, warp_n = wid >> 1;
    const int g = lane >> 3, lr = lane & 7;

    uint32_t arow64[4], axr[4], brow64[2], bxr[2];
    const uint32_t ac0 = (uint32_t)(g >> 1);
    const uint32_t bc0 = (uint32_t)(g & 1);
    #pragma unroll
    for (int mt = 0; mt < 4; mt++) {
        const uint32_t r = (uint32_t)(warp_m * 64 + mt * 16 + (g & 1) * 8 + lr);
        arow64[mt] = r * 64;
        axr[mt] = (r >> 1) & 3u;
    }
    #pragma unroll
    for (int np = 0; np < 2; np++) {
        const uint32_t r = (uint32_t)(warp_n * 32 + np * 16 + (g >> 1) * 8 + lr);
        brow64[np] = r * 64;
        bxr[np] = (r >> 1) & 3u;
    }

    #pragma unroll
    for (int mt = 0; mt < 4; mt++)
        #pragma unroll
        for (int nt = 0; nt < 4; nt++)
            #pragma unroll
            for (int i = 0; i < 4; i++) acc[mt][nt][i] = 0.f;

    const int NCH = C_ / 32;   // 32 chunks
    stage_load(sb,            Ah, Al, Bh, Bl, a_row0, b_row0, 0,  t);
    CP_COMMIT();
    stage_load(sb + SSTG,     Ah, Al, Bh, Bl, a_row0, b_row0, 32, t);
    CP_COMMIT();
    uint32_t slot = 0;   // slot index of chunk i
    for (int i = 0; i < NCH; i++) {
        CP_WAIT(1);
        __syncthreads();
        if (i + 2 < NCH) {
            uint32_t nslot = slot + 2; if (nslot >= 3) nslot -= 3;
            stage_load(sb + nslot * SSTG, Ah, Al, Bh, Bl,
                       a_row0, b_row0, (i + 2) * 32, t);
        }
        CP_COMMIT();   // may be empty: keeps group count uniform
        stage_compute(sb + slot * SSTG, arow64, axr, ac0, brow64, bxr, bc0, acc);
        if (++slot == 3) slot = 0;
    }
}

// Fused QKV GEMM: [8192,1024] @ [1024,3072]; grid (64, 24), block 256.
__global__ __launch_bounds__(256, 2) void qkv_mma_kernel()
{
    extern __shared__ __align__(16) unsigned char dynsmem[];
    const uint32_t sb = smem_u32(dynsmem);
    const int m0 = blockIdx.x * 128;
    const int n0 = blockIdx.y * 128;

    float acc[4][4][4];
    gemm_mainloop(g_xhi, g_xlo, g_wthi, g_wtlo, m0, n0, sb, acc);

    const int wid = threadIdx.x >> 5, lane = threadIdx.x & 31;
    const int warp_m = wid & 1, warp_n = wid >> 1;
    const int qr = lane >> 2, qc2 = (lane & 3) * 2;

    // q pre-scale: 1/sqrt(64) * log2(e)  (softmax done in exp2 domain)
    const float QSCALE = 0.125f * 1.4426950408889634f;

    #pragma unroll
    for (int nt = 0; nt < 4; nt++) {
        const int gn = n0 + warp_n * 32 + nt * 8 + qc2;
        const int z = gn >> 6, d = gn & 63;
        const int p = z >> 4, h = z & 15;
        __nv_bfloat16* outh = (p == 0 ? g_qh : (p == 1 ? g_kh : g_vh));
        __nv_bfloat16* outl = (p == 0 ? g_ql : (p == 1 ? g_kl : g_vl));
        const float scale = (p == 0) ? QSCALE : 1.0f;
        #pragma unroll
        for (int mt = 0; mt < 4; mt++) {
            #pragma unroll
            for (int rh = 0; rh < 2; rh++) {
                const int gm = m0 + warp_m * 64 + mt * 16 + qr + rh * 8;
                const int b = gm >> 11, tt = gm & (T_ - 1);
                const size_t idx = ((size_t)(b * H_ + h) * T_ + tt) * HS_ + d;
                float v0 = acc[mt][nt][rh * 2] * scale;
                float v1 = acc[mt][nt][rh * 2 + 1] * scale;
                float h0 = __bfloat162float(__float2bfloat16(v0));
                float h1 = __bfloat162float(__float2bfloat16(v1));
                *(uint32_t*)&outh[idx] = packbf(h0, h1);
                *(uint32_t*)&outl[idx] = packbf(v0 - h0, v1 - h1);
            }
        }
    }
}

// Output projection: [8192,1024] @ [1024,1024]; grid (64, 8), block 256.
__global__ __launch_bounds__(256, 2) void proj_mma_kernel(
    const float* __restrict__ bo, float* __restrict__ out)
{
    extern __shared__ __align__(16) unsigned char dynsmem[];
    const uint32_t sb = smem_u32(dynsmem);
    const int m0 = blockIdx.x * 128;
    const int n0 = blockIdx.y * 128;

    float acc[4][4][4];
    gemm_mainloop(g_ahi, g_alo, g_wohi, g_wolo, m0, n0, sb, acc);

    const int wid = threadIdx.x >> 5, lane = threadIdx.x & 31;
    const int warp_m = wid & 1, warp_n = wid >> 1;
    const int qr = lane >> 2, qc2 = (lane & 3) * 2;

    #pragma unroll
    for (int nt = 0; nt < 4; nt++) {
        const int gn = n0 + warp_n * 32 + nt * 8 + qc2;
        const float2 bb = *(const float2*)&bo[gn];
        #pragma unroll
        for (int mt = 0; mt < 4; mt++) {
            #pragma unroll
            for (int rh = 0; rh < 2; rh++) {
                const int gm = m0 + warp_m * 64 + mt * 16 + qr + rh * 8;
                *(float2*)(out + (size_t)gm * C_ + gn) =
                    make_float2(acc[mt][nt][rh * 2] + bb.x,
                                acc[mt][nt][rh * 2 + 1] + bb.y);
            }
        }
    }
}

// ---------------------------------------------------------------------------
// HMMA causal flash attention with cp.async double-buffered K/V stages.
// CTA: 64 q-rows x one bh, 4 warps. Softmax in exp2 domain (q pre-scaled).
// S = QK^T 3-term; O = PV 3-term (P hi/lo, V hi/lo) — P hi/lo is required
// for rel_err < 1e-3 (R9 post-mortem: plain-bf16 P gives 1.3e-3).
// ---------------------------------------------------------------------------
#define QSTR 144
#define AQ_   (64 * QSTR)        // 9216 per buffer
#define AKV_STG (4 * AQ_)        // 36864 per stage
#define ASMEM (2 * AQ_ + 2 * AKV_STG)   // 92160

__device__ __forceinline__ void attn_stage_kv(uint32_t st, size_t base,
                                              int j0, int t)
{
    const int crow = t >> 1;
    const int coff = (t & 1) * 64;   // bytes
    const uint32_t doff = (uint32_t)crow * QSTR + coff;
    const __nv_bfloat16* pkh = g_kh + base + (size_t)(j0 + crow) * HS_ + (coff >> 1);
    const __nv_bfloat16* pkl = g_kl + base + (size_t)(j0 + crow) * HS_ + (coff >> 1);
    const __nv_bfloat16* pvh = g_vh + base + (size_t)(j0 + crow) * HS_ + (coff >> 1);
    const __nv_bfloat16* pvl = g_vl + base + (size_t)(j0 + crow) * HS_ + (coff >> 1);
    #pragma unroll
    for (int j = 0; j < 4; j++) {
        cp16(st + 0 * AQ_ + doff + j * 16, pkh + j * 8);
        cp16(st + 1 * AQ_ + doff + j * 16, pkl + j * 8);
        cp16(st + 2 * AQ_ + doff + j * 16, pvh + j * 8);
        cp16(st + 3 * AQ_ + doff + j * 16, pvl + j * 8);
    }
}

__global__ __launch_bounds__(128) void attn_hmma_kernel()
{
    extern __shared__ __align__(16) unsigned char dynsmem[];
    const uint32_t sb = smem_u32(dynsmem);
    const uint32_t uQh = sb, uQl = sb + AQ_;
    unsigned char* sQh = dynsmem;
    unsigned char* sQl = dynsmem + AQ_;

    const int bh = blockIdx.y;
    const int r0 = blockIdx.x * 64;
    const int t  = threadIdx.x;
    const int w  = t >> 5, lane = t & 31;
    const int g = lane >> 3, lr = lane & 7;
    const int qr = lane >> 2, qc = lane & 3;

    const size_t base = (size_t)bh * T_ * HS_;

    const int crow = t >> 1;
    const int coff = (t & 1) * 64;

    // ---- prefetch KV tile 0 (stage 0)
    attn_stage_kv(sb + 2 * AQ_, base, 0, t);
    CP_COMMIT();

    // ---- prologue: Q tile -> smem -> fragments
    {
        const unsigned char* gh =
            (const unsigned char*)(g_qh + base + (size_t)(r0 + crow) * HS_) + coff;
        const unsigned char* gl =
            (const unsigned char*)(g_ql + base + (size_t)(r0 + crow) * HS_) + coff;
        uint4 a0 = ((const uint4*)gh)[0], a1 = ((const uint4*)gh)[1];
        uint4 a2 = ((const uint4*)gh)[2], a3 = ((const uint4*)gh)[3];
        uint4 b0 = ((const uint4*)gl)[0], b1 = ((const uint4*)gl)[1];
        uint4 b2 = ((const uint4*)gl)[2], b3 = ((const uint4*)gl)[3];
        uint4* dh = (uint4*)(sQh + crow * QSTR + coff);
        uint4* dl = (uint4*)(sQl + crow * QSTR + coff);
        dh[0] = a0; dh[1] = a1; dh[2] = a2; dh[3] = a3;
        dl[0] = b0; dl[1] = b1; dl[2] = b2; dl[3] = b3;
    }
    __syncthreads();

    uint32_t qh[4][4], ql[4][4];
    {
        const uint32_t qoff = (uint32_t)(w * 16 + (g & 1) * 8 + lr) * QSTR
                            + (uint32_t)((g >> 1) * 8) * 2;
        #pragma unroll
        for (int ks = 0; ks < 4; ks++) {
            ldsm4(qh[ks], uQh + qoff + ks * 32);
            ldsm4(ql[ks], uQl + qoff + ks * 32);
        }
    }

    float accO[8][4];
    #pragma unroll
    for (int nt = 0; nt < 8; nt++)
        #pragma unroll
        for (int i = 0; i < 4; i++) accO[nt][i] = 0.f;
    float mrow[2] = {-1e30f, -1e30f};
    float lrow[2] = {0.f, 0.f};

    uint32_t koff[4];
    #pragma unroll
    for (int np = 0; np < 4; np++)
        koff[np] = (uint32_t)(np * 16 + (g >> 1) * 8 + lr) * QSTR
                 + (uint32_t)((g & 1) * 8) * 2;
    const uint32_t vrow = (uint32_t)((g & 1) * 8 + lr);
    const uint32_t vcol = (uint32_t)((g >> 1) * 8) * 2;

    const int ntiles = (r0 >> 6) + 1;
    for (int i = 0; i < ntiles; i++) {
        CP_WAIT(0);
        __syncthreads();
        if (i + 1 < ntiles) {
            attn_stage_kv(sb + 2 * AQ_ + (uint32_t)((i + 1) & 1) * AKV_STG,
                          base, (i + 1) * 64, t);
            CP_COMMIT();
        }
        const uint32_t st = sb + 2 * AQ_ + (uint32_t)(i & 1) * AKV_STG;
        const uint32_t uKh = st, uKl = st + AQ_;
        const uint32_t uVh = st + 2 * AQ_, uVl = st + 3 * AQ_;
        const int j0 = i * 64;

        float accS[8][4];
        #pragma unroll
        for (int nt = 0; nt < 8; nt++)
            #pragma unroll
            for (int ii = 0; ii < 4; ii++) accS[nt][ii] = 0.f;

        #pragma unroll
        for (int ks = 0; ks < 4; ks++) {
            #pragma unroll
            for (int np = 0; np < 4; np++) {
                uint32_t kfh[4], kfl[4];
                ldsm4(kfh, uKh + koff[np] + ks * 32);
                ldsm4(kfl, uKl + koff[np] + ks * 32);
                #pragma unroll
                for (int hf = 0; hf < 2; hf++) {
                    const int nt = np * 2 + hf;
                    mma16816(accS[nt], qh[ks], kfh[hf * 2], kfh[hf * 2 + 1]);
                    mma16816(accS[nt], qh[ks], kfl[hf * 2], kfl[hf * 2 + 1]);
                    mma16816(accS[nt], ql[ks], kfh[hf * 2], kfh[hf * 2 + 1]);
                }
            }
        }

        if (j0 == r0) {
            #pragma unroll
            for (int nt = 0; nt < 8; nt++)
                #pragma unroll
                for (int ii = 0; ii < 4; ii++) {
                    const int col = nt * 8 + qc * 2 + (ii & 1);
                    const int rr = w * 16 + qr + (ii >> 1) * 8;
                    if (col > rr) accS[nt][ii] = -1e30f;
                }
        }

        // softmax in exp2 domain (log2e folded into q)
        float corr[2];
        #pragma unroll
        for (int hrow = 0; hrow < 2; hrow++) {
            float mx = -1e30f;
            #pragma unroll
            for (int nt = 0; nt < 8; nt++) {
                mx = fmaxf(mx, fmaxf(accS[nt][hrow * 2], accS[nt][hrow * 2 + 1]));
            }
            mx = fmaxf(mx, __shfl_xor_sync(0xffffffffu, mx, 1));
            mx = fmaxf(mx, __shfl_xor_sync(0xffffffffu, mx, 2));
            const float m_new = fmaxf(mrow[hrow], mx);
            corr[hrow] = ex2(mrow[hrow] - m_new);
            mrow[hrow] = m_new;
            float rs = 0.f;
            #pragma unroll
            for (int nt = 0; nt < 8; nt++) {
                float p0 = ex2(accS[nt][hrow * 2]     - m_new);
                float p1 = ex2(accS[nt][hrow * 2 + 1] - m_new);
                accS[nt][hrow * 2]     = p0;
                accS[nt][hrow * 2 + 1] = p1;
                rs += p0 + p1;
            }
            rs += __shfl_xor_sync(0xffffffffu, rs, 1);
            rs += __shfl_xor_sync(0xffffffffu, rs, 2);
            lrow[hrow] = lrow[hrow] * corr[hrow] + rs;
        }
        #pragma unroll
        for (int nt = 0; nt < 8; nt++) {
            accO[nt][0] *= corr[0]; accO[nt][1] *= corr[0];
            accO[nt][2] *= corr[1]; accO[nt][3] *= corr[1];
        }

        // O += P V  (P hi/lo, V hi/lo -> 3 terms)
        #pragma unroll
        for (int ks = 0; ks < 4; ks++) {
            uint32_t pfh[4], pfl[4];
            #pragma unroll
            for (int half = 0; half < 2; half++) {
                const int nt = ks * 2 + half;
                #pragma unroll
                for (int rh = 0; rh < 2; rh++) {
                    float v0 = accS[nt][rh * 2], v1 = accS[nt][rh * 2 + 1];
                    float h0 = __bfloat162float(__float2bfloat16(v0));
                    float h1 = __bfloat162float(__float2bfloat16(v1));
                    pfh[half * 2 + rh] = packbf(h0, h1);
                    pfl[half * 2 + rh] = packbf(v0 - h0, v1 - h1);
                }
            }
            #pragma unroll
            for (int np = 0; np < 4; np++) {
                uint32_t vfh[4], vfl[4];
                const uint32_t va = (vrow + ks * 16) * QSTR + np * 32 + vcol;
                ldsm4t(vfh, uVh + va);
                ldsm4t(vfl, uVl + va);
                #pragma unroll
                for (int hf = 0; hf < 2; hf++) {
                    const int nt = np * 2 + hf;
                    mma16816(accO[nt], pfh, vfh[hf * 2], vfh[hf * 2 + 1]);
                    mma16816(accO[nt], pfh, vfl[hf * 2], vfl[hf * 2 + 1]);
                    mma16816(accO[nt], pfl, vfh[hf * 2], vfh[hf * 2 + 1]);
                }
            }
        }
        __syncthreads();
    }

    const float inv0 = 1.f / lrow[0];
    const float inv1 = 1.f / lrow[1];
    const int b = bh >> 4, hh = bh & 15;
    #pragma unroll
    for (int nt = 0; nt < 8; nt++) {
        const int d = hh * 64 + nt * 8 + qc * 2;
        #pragma unroll
        for (int rh = 0; rh < 2; rh++) {
            const float inv = rh ? inv1 : inv0;
            const int row = r0 + w * 16 + qr + rh * 8;
            const size_t idx = (size_t)(b * T_ + row) * C_ + d;
            float v0 = accO[nt][rh * 2] * inv;
            float v1 = accO[nt][rh * 2 + 1] * inv;
            float h0 = __bfloat162float(__float2bfloat16(v0));
            float h1 = __bfloat162float(__float2bfloat16(v1));
            *(uint32_t*)&g_ahi[idx] = packbf(h0, h1);
            *(uint32_t*)&g_alo[idx] = packbf(v0 - h0, v1 - h1);
        }
    }
}

// ---------------------------------------------------------------------------
extern "C" void kernel_launch(void* const* d_in, const int* in_sizes, int n_in,
                              void* d_out, int out_size)
{
    const float* x  = (const float*)d_in[0];
    const float* Wq = (const float*)d_in[1];
    const float* Wk = (const float*)d_in[2];
    const float* Wv = (const float*)d_in[3];
    const float* Wo = (const float*)d_in[4];
    const float* bo = (const float*)d_in[5];
    float* out = (float*)d_out;

    __nv_bfloat16 *xhi, *xlo, *wohi, *wolo;
    cudaGetSymbolAddress((void**)&xhi,  g_xhi);
    cudaGetSymbolAddress((void**)&xlo,  g_xlo);
    cudaGetSymbolAddress((void**)&wohi, g_wohi);
    cudaGetSymbolAddress((void**)&wolo, g_wolo);

    cudaFuncSetAttribute(qkv_mma_kernel,
        cudaFuncAttributeMaxDynamicSharedMemorySize, GSMEM);
    cudaFuncSetAttribute(proj_mma_kernel,
        cudaFuncAttributeMaxDynamicSharedMemorySize, GSMEM);
    cudaFuncSetAttribute(attn_hmma_kernel,
        cudaFuncAttributeMaxDynamicSharedMemorySize, ASMEM);

    split_kernel<<<(B_ * T_ * C_ / 4 + 255) / 256, 256>>>(x, xhi, xlo, B_ * T_ * C_ / 4);
    split_wqkv_kernel<<<dim3(HS_ * C_ / 256, 48), 256>>>(Wq, Wk, Wv);
    split_kernel<<<(C_ * C_ / 4 + 255) / 256, 256>>>(Wo, wohi, wolo, C_ * C_ / 4);

    qkv_mma_kernel<<<dim3(B_ * T_ / 128, 3 * C_ / 128), 256, GSMEM>>>();

    attn_hmma_kernel<<<dim3(T_ / 64, B_ * H_), 128, ASMEM>>>();

    proj_mma_kernel<<<dim3(B_ * T_ / 128, C_ / 128), 256, GSMEM>>>(bo, out);
}

// round 12
// speedup vs baseline: 1.3712x; 1.0935x over previous
#include <cuda_runtime.h>
#include <cuda_bf16.h>
#include <cstdint>

#define B_  4
#define T_  2048
#define C_  1024
#define H_  16
#define HS_ 64

// ---------------------------------------------------------------------------
// Scratch (allocation-free rule: __device__ globals)
// ---------------------------------------------------------------------------
__device__ __nv_bfloat16 g_xhi[B_ * T_ * C_];
__device__ __nv_bfloat16 g_xlo[B_ * T_ * C_];
__device__ __nv_bfloat16 g_wthi[3 * H_ * HS_ * C_];   // [n=z*64+d][c] K-major
__device__ __nv_bfloat16 g_wtlo[3 * H_ * HS_ * C_];
__device__ __nv_bfloat16 g_wohi[C_ * C_];             // [n][k]
__device__ __nv_bfloat16 g_wolo[C_ * C_];
__device__ __nv_bfloat16 g_ahi[B_ * T_ * C_];
__device__ __nv_bfloat16 g_alo[B_ * T_ * C_];

// q/k/v in bf16 hi/lo, layout [bh][t][64]; q pre-scaled by log2e/sqrt(HS)
__device__ __nv_bfloat16 g_qh[B_ * H_ * T_ * HS_];
__device__ __nv_bfloat16 g_ql[B_ * H_ * T_ * HS_];
__device__ __nv_bfloat16 g_kh[B_ * H_ * T_ * HS_];
__device__ __nv_bfloat16 g_kl[B_ * H_ * T_ * HS_];
__device__ __nv_bfloat16 g_vh[B_ * H_ * T_ * HS_];
__device__ __nv_bfloat16 g_vl[B_ * H_ * T_ * HS_];

// ---------------------------------------------------------------------------
// Portable tensor-core primitives (sm_80+ ISA; compiles at base compute_103)
// ---------------------------------------------------------------------------
__device__ __forceinline__ uint32_t smem_u32(const void* p) {
    uint32_t a;
    asm("{ .reg .u64 t; cvta.to.shared.u64 t, %1; cvt.u32.u64 %0, t; }"
        : "=r"(a) : "l"(p));
    return a;
}

__device__ __forceinline__ void ldsm4(uint32_t* r, uint32_t addr) {
    asm volatile("ldmatrix.sync.aligned.m8n8.x4.shared.b16 {%0,%1,%2,%3}, [%4];"
        : "=r"(r[0]), "=r"(r[1]), "=r"(r[2]), "=r"(r[3]) : "r"(addr));
}

__device__ __forceinline__ void ldsm4t(uint32_t* r, uint32_t addr) {
    asm volatile("ldmatrix.sync.aligned.m8n8.x4.trans.shared.b16 {%0,%1,%2,%3}, [%4];"
        : "=r"(r[0]), "=r"(r[1]), "=r"(r[2]), "=r"(r[3]) : "r"(addr));
}

__device__ __forceinline__ void mma16816(float* c, const uint32_t* a,
                                         const uint32_t b0, const uint32_t b1) {
    asm volatile(
        "mma.sync.aligned.m16n8k16.row.col.f32.bf16.bf16.f32 "
        "{%0,%1,%2,%3}, {%4,%5,%6,%7}, {%8,%9}, {%0,%1,%2,%3};"
        : "+f"(c[0]), "+f"(c[1]), "+f"(c[2]), "+f"(c[3])
        : "r"(a[0]), "r"(a[1]), "r"(a[2]), "r"(a[3]), "r"(b0), "r"(b1));
}

__device__ __forceinline__ uint32_t packbf(float a, float b) {
    __nv_bfloat162 t = __floats2bfloat162_rn(a, b);
    return *(uint32_t*)&t;
}

__device__ __forceinline__ float ex2(float x) {
    float r;
    asm("ex2.approx.ftz.f32 %0, %1;" : "=f"(r) : "f"(x));
    return r;
}

__device__ __forceinline__ void cp16(uint32_t dst, const void* src) {
    asm volatile("cp.async.cg.shared.global [%0], [%1], 16;"
        :: "r"(dst), "l"(src) : "memory");
}
#define CP_COMMIT() asm volatile("cp.async.commit_group;" ::: "memory")
#define CP_WAIT(n)  asm volatile("cp.async.wait_group %0;" :: "n"(n) : "memory")

// ---------------------------------------------------------------------------
// fp32 -> bf16 hi/lo split kernels
// ---------------------------------------------------------------------------
struct __align__(8) bf4 { __nv_bfloat16 a, b, c, d; };

__device__ __forceinline__ void split4(float4 v, bf4& hv, bf4& lv) {
    __nv_bfloat16 h0 = __float2bfloat16(v.x);
    __nv_bfloat16 h1 = __float2bfloat16(v.y);
    __nv_bfloat16 h2 = __float2bfloat16(v.z);
    __nv_bfloat16 h3 = __float2bfloat16(v.w);
    hv = {h0, h1, h2, h3};
    lv = {__float2bfloat16(v.x - __bfloat162float(h0)),
          __float2bfloat16(v.y - __bfloat162float(h1)),
          __float2bfloat16(v.z - __bfloat162float(h2)),
          __float2bfloat16(v.w - __bfloat162float(h3))};
}

__global__ __launch_bounds__(256) void split_kernel(
    const float* __restrict__ in,
    __nv_bfloat16* __restrict__ hi,
    __nv_bfloat16* __restrict__ lo, int n4)
{
    int i = blockIdx.x * blockDim.x + threadIdx.x;
    if (i >= n4) return;
    bf4 hv, lv;
    split4(((const float4*)in)[i], hv, lv);
    ((bf4*)hi)[i] = hv;
    ((bf4*)lo)[i] = lv;
}

// W[h][c][d] (fp32) -> Wt[z][d][c] (bf16 hi/lo), z = p*16+h
__global__ __launch_bounds__(256) void split_wqkv_kernel(
    const float* __restrict__ Wq,
    const float* __restrict__ Wk,
    const float* __restrict__ Wv)
{
    int z = blockIdx.y;
    int p = z >> 4, h = z & 15;
    const float* W = (p == 0 ? Wq : (p == 1 ? Wk : Wv)) + (size_t)h * C_ * HS_;
    int idx = blockIdx.x * blockDim.x + threadIdx.x;
    int d = idx & 63;
    int c = idx >> 6;
    float v = W[(size_t)c * HS_ + d];
    __nv_bfloat16 hv = __float2bfloat16(v);
    __nv_bfloat16 lv = __float2bfloat16(v - __bfloat162float(hv));
    size_t o = ((size_t)z * HS_ + d) * C_ + c;
    g_wthi[o] = hv;
    g_wtlo[o] = lv;
}

// ---------------------------------------------------------------------------
// Pipelined HMMA GEMM: CTA 128x128, warp tile 64x32 (8 warps, 2x4), BK=32,
// 3-stage cp.async pipeline, XOR-swizzled smem (64B rows, conflict-free),
// ONE __syncthreads per chunk. A,B K-major bf16 hi/lo.
// ---------------------------------------------------------------------------
#define SOFF_AH 0
#define SOFF_AL 8192
#define SOFF_BH 16384
#define SOFF_BL 24576
#define SSTG    32768
#define GSMEM   (3 * SSTG)   // 98304

__device__ __forceinline__ uint32_t swz(uint32_t row, uint32_t c16) {
    return row * 64 + (((c16 ^ (row >> 1)) & 3u) << 4);
}

__device__ __forceinline__ void stage_load(
    uint32_t sbase,
    const __nv_bfloat16* __restrict__ Ah, const __nv_bfloat16* __restrict__ Al,
    const __nv_bfloat16* __restrict__ Bh, const __nv_bfloat16* __restrict__ Bl,
    int a_row0, int b_row0, int k0, int t)
{
    const uint32_t row = (uint32_t)(t >> 1);
    const uint32_t c0  = (uint32_t)(t & 1) * 2;      // c16 base {0,2}
    const uint32_t s0 = swz(row, c0), s1 = swz(row, c0 + 1);
    const size_t ga = (size_t)(a_row0 + (int)row) * C_ + k0 + (int)c0 * 8;
    const size_t gb = (size_t)(b_row0 + (int)row) * C_ + k0 + (int)c0 * 8;
    cp16(sbase + SOFF_AH + s0, Ah + ga);
    cp16(sbase + SOFF_AH + s1, Ah + ga + 8);
    cp16(sbase + SOFF_AL + s0, Al + ga);
    cp16(sbase + SOFF_AL + s1, Al + ga + 8);
    cp16(sbase + SOFF_BH + s0, Bh + gb);
    cp16(sbase + SOFF_BH + s1, Bh + gb + 8);
    cp16(sbase + SOFF_BL + s0, Bl + gb);
    cp16(sbase + SOFF_BL + s1, Bl + gb + 8);
}

__device__ __forceinline__ void stage_compute(
    uint32_t sbase,
    const uint32_t arow64[4], const uint32_t axr[4], uint32_t ac0,
    const uint32_t brow64[2], const uint32_t bxr[2], uint32_t bc0,
    float acc[4][4][4])
{
    #pragma unroll
    for (int kk = 0; kk < 2; kk++) {
        uint32_t ah[4][4], al[4][4];
        #pragma unroll
        for (int mt = 0; mt < 4; mt++) {
            const uint32_t ca = (((ac0 + 2 * kk) ^ axr[mt]) & 3u) << 4;
            ldsm4(ah[mt], sbase + SOFF_AH + arow64[mt] + ca);
            ldsm4(al[mt], sbase + SOFF_AL + arow64[mt] + ca);
        }
        #pragma unroll
        for (int np = 0; np < 2; np++) {
            const uint32_t cb = (((bc0 + 2 * kk) ^ bxr[np]) & 3u) << 4;
            uint32_t bh[4], bl[4];
            ldsm4(bh, sbase + SOFF_BH + brow64[np] + cb);
            ldsm4(bl, sbase + SOFF_BL + brow64[np] + cb);
            #pragma unroll
            for (int mt = 0; mt < 4; mt++)
                #pragma unroll
                for (int hf = 0; hf < 2; hf++) {
                    const int nt = np * 2 + hf;
                    mma16816(acc[mt][nt], ah[mt], bh[hf * 2], bh[hf * 2 + 1]);
                    mma16816(acc[mt][nt], ah[mt], bl[hf * 2], bl[hf * 2 + 1]);
                    mma16816(acc[mt][nt], al[mt], bh[hf * 2], bh[hf * 2 + 1]);
                }
        }
    }
}

__device__ __forceinline__ void gemm_mainloop(
    const __nv_bfloat16* __restrict__ Ah, const __nv_bfloat16* __restrict__ Al,
    const __nv_bfloat16* __restrict__ Bh, const __nv_bfloat16* __restrict__ Bl,
    int a_row0, int b_row0, uint32_t sb, float acc[4][4][4])
{
    const int t = threadIdx.x;
    const int wid = t >> 5, lane = t & 31;
    const int warp_m = wid & 1, warp_n = wid >> 1;
    const int g = lane >> 3, lr = lane & 7;

    uint32_t arow64[4], axr[4], brow64[2], bxr[2];
    const uint32_t ac0 = (uint32_t)(g >> 1);
    const uint32_t bc0 = (uint32_t)(g & 1);
    #pragma unroll
    for (int mt = 0; mt < 4; mt++) {
        const uint32_t r = (uint32_t)(warp_m * 64 + mt * 16 + (g & 1) * 8 + lr);
        arow64[mt] = r * 64;
        axr[mt] = (r >> 1) & 3u;
    }
    #pragma unroll
    for (int np = 0; np < 2; np++) {
        const uint32_t r = (uint32_t)(warp_n * 32 + np * 16 + (g >> 1) * 8 + lr);
        brow64[np] = r * 64;
        bxr[np] = (r >> 1) & 3u;
    }

    #pragma unroll
    for (int mt = 0; mt < 4; mt++)
        #pragma unroll
        for (int nt = 0; nt < 4; nt++)
            #pragma unroll
            for (int i = 0; i < 4; i++) acc[mt][nt][i] = 0.f;

    const int NCH = C_ / 32;   // 32 chunks
    stage_load(sb,            Ah, Al, Bh, Bl, a_row0, b_row0, 0,  t);
    CP_COMMIT();
    stage_load(sb + SSTG,     Ah, Al, Bh, Bl, a_row0, b_row0, 32, t);
    CP_COMMIT();
    uint32_t slot = 0;   // slot index of chunk i
    for (int i = 0; i < NCH; i++) {
        CP_WAIT(1);
        __syncthreads();
        if (i + 2 < NCH) {
            uint32_t nslot = slot + 2; if (nslot >= 3) nslot -= 3;
            stage_load(sb + nslot * SSTG, Ah, Al, Bh, Bl,
                       a_row0, b_row0, (i + 2) * 32, t);
        }
        CP_COMMIT();   // may be empty: keeps group count uniform
        stage_compute(sb + slot * SSTG, arow64, axr, ac0, brow64, bxr, bc0, acc);
        if (++slot == 3) slot = 0;
    }
}

// Fused QKV GEMM: [8192,1024] @ [1024,3072]; grid (64, 24), block 256.
__global__ __launch_bounds__(256, 2) void qkv_mma_kernel()
{
    extern __shared__ __align__(16) unsigned char dynsmem[];
    const uint32_t sb = smem_u32(dynsmem);
    const int m0 = blockIdx.x * 128;
    const int n0 = blockIdx.y * 128;

    float acc[4][4][4];
    gemm_mainloop(g_xhi, g_xlo, g_wthi, g_wtlo, m0, n0, sb, acc);

    const int wid = threadIdx.x >> 5, lane = threadIdx.x & 31;
    const int warp_m = wid & 1, warp_n = wid >> 1;
    const int qr = lane >> 2, qc2 = (lane & 3) * 2;

    // q pre-scale: 1/sqrt(64) * log2(e)  (softmax done in exp2 domain)
    const float QSCALE = 0.125f * 1.4426950408889634f;

    #pragma unroll
    for (int nt = 0; nt < 4; nt++) {
        const int gn = n0 + warp_n * 32 + nt * 8 + qc2;
        const int z = gn >> 6, d = gn & 63;
        const int p = z >> 4, h = z & 15;
        __nv_bfloat16* outh = (p == 0 ? g_qh : (p == 1 ? g_kh : g_vh));
        __nv_bfloat16* outl = (p == 0 ? g_ql : (p == 1 ? g_kl : g_vl));
        const float scale = (p == 0) ? QSCALE : 1.0f;
        #pragma unroll
        for (int mt = 0; mt < 4; mt++) {
            #pragma unroll
            for (int rh = 0; rh < 2; rh++) {
                const int gm = m0 + warp_m * 64 + mt * 16 + qr + rh * 8;
                const int b = gm >> 11, tt = gm & (T_ - 1);
                const size_t idx = ((size_t)(b * H_ + h) * T_ + tt) * HS_ + d;
                float v0 = acc[mt][nt][rh * 2] * scale;
                float v1 = acc[mt][nt][rh * 2 + 1] * scale;
                float h0 = __bfloat162float(__float2bfloat16(v0));
                float h1 = __bfloat162float(__float2bfloat16(v1));
                *(uint32_t*)&outh[idx] = packbf(h0, h1);
                *(uint32_t*)&outl[idx] = packbf(v0 - h0, v1 - h1);
            }
        }
    }
}

// Output projection: [8192,1024] @ [1024,1024]; grid (64, 8), block 256.
__global__ __launch_bounds__(256, 2) void proj_mma_kernel(
    const float* __restrict__ bo, float* __restrict__ out)
{
    extern __shared__ __align__(16) unsigned char dynsmem[];
    const uint32_t sb = smem_u32(dynsmem);
    const int m0 = blockIdx.x * 128;
    const int n0 = blockIdx.y * 128;

    float acc[4][4][4];
    gemm_mainloop(g_ahi, g_alo, g_wohi, g_wolo, m0, n0, sb, acc);

    const int wid = threadIdx.x >> 5, lane = threadIdx.x & 31;
    const int warp_m = wid & 1, warp_n = wid >> 1;
    const int qr = lane >> 2, qc2 = (lane & 3) * 2;

    #pragma unroll
    for (int nt = 0; nt < 4; nt++) {
        const int gn = n0 + warp_n * 32 + nt * 8 + qc2;
        const float2 bb = *(const float2*)&bo[gn];
        #pragma unroll
        for (int mt = 0; mt < 4; mt++) {
            #pragma unroll
            for (int rh = 0; rh < 2; rh++) {
                const int gm = m0 + warp_m * 64 + mt * 16 + qr + rh * 8;
                *(float2*)(out + (size_t)gm * C_ + gn) =
                    make_float2(acc[mt][nt][rh * 2] + bb.x,
                                acc[mt][nt][rh * 2 + 1] + bb.y);
            }
        }
    }
}

// ---------------------------------------------------------------------------
// HMMA causal flash attention, 128 q-rows per CTA, 8 warps (256 threads).
// Warp w owns rows [r0+w*16, r0+w*16+16) with FULL S rows (softmax intact).
// K/V hi/lo cp.async double-buffered; softmax in exp2 domain.
// S = QK^T 3-term; O = PV 3-term (P hi/lo required: R9 post-mortem).
// ---------------------------------------------------------------------------
#define QSTR 144
#define AQB   (128 * QSTR)       // 18432 per Q buffer (hi, lo)
#define AKV   (64 * QSTR)        // 9216 per KV buffer
#define AKV_STG (4 * AKV)        // 36864 per stage
#define ASMEM (2 * AQB + 2 * AKV_STG)   // 110592

__device__ __forceinline__ void attn_stage_kv(uint32_t st, size_t base,
                                              int j0, int t)
{
    const int crow = t >> 2;          // 0..63 (4 threads per row)
    const int coff = (t & 3) * 32;    // byte quarter of 128-byte row
    const uint32_t doff = (uint32_t)crow * QSTR + coff;
    const __nv_bfloat16* pkh = g_kh + base + (size_t)(j0 + crow) * HS_ + (coff >> 1);
    const __nv_bfloat16* pkl = g_kl + base + (size_t)(j0 + crow) * HS_ + (coff >> 1);
    const __nv_bfloat16* pvh = g_vh + base + (size_t)(j0 + crow) * HS_ + (coff >> 1);
    const __nv_bfloat16* pvl = g_vl + base + (size_t)(j0 + crow) * HS_ + (coff >> 1);
    cp16(st + 0 * AKV + doff,      pkh);
    cp16(st + 0 * AKV + doff + 16, pkh + 8);
    cp16(st + 1 * AKV + doff,      pkl);
    cp16(st + 1 * AKV + doff + 16, pkl + 8);
    cp16(st + 2 * AKV + doff,      pvh);
    cp16(st + 2 * AKV + doff + 16, pvh + 8);
    cp16(st + 3 * AKV + doff,      pvl);
    cp16(st + 3 * AKV + doff + 16, pvl + 8);
}

__global__ __launch_bounds__(256, 2) void attn_hmma_kernel()
{
    extern __shared__ __align__(16) unsigned char dynsmem[];
    const uint32_t sb = smem_u32(dynsmem);
    const uint32_t uQh = sb, uQl = sb + AQB;
    unsigned char* sQh = dynsmem;
    unsigned char* sQl = dynsmem + AQB;
    const uint32_t kvbase = sb + 2 * AQB;

    const int bh = blockIdx.y;
    const int r0 = blockIdx.x * 128;
    const int t  = threadIdx.x;
    const int w  = t >> 5, lane = t & 31;
    const int g = lane >> 3, lr = lane & 7;
    const int qr = lane >> 2, qc = lane & 3;

    const size_t base = (size_t)bh * T_ * HS_;
    const int wr0 = r0 + w * 16;      // first global row of this warp's slab

    // ---- prefetch KV tile 0 (stage 0)
    attn_stage_kv(kvbase, base, 0, t);
    CP_COMMIT();

    // ---- prologue: Q tile (128 rows) -> smem -> fragments
    {
        const int crow = t >> 1;           // 0..127
        const int coff = (t & 1) * 64;
        const unsigned char* gh =
            (const unsigned char*)(g_qh + base + (size_t)(r0 + crow) * HS_) + coff;
        const unsigned char* gl =
            (const unsigned char*)(g_ql + base + (size_t)(r0 + crow) * HS_) + coff;
        uint4 a0 = ((const uint4*)gh)[0], a1 = ((const uint4*)gh)[1];
        uint4 a2 = ((const uint4*)gh)[2], a3 = ((const uint4*)gh)[3];
        uint4 b0 = ((const uint4*)gl)[0], b1 = ((const uint4*)gl)[1];
        uint4 b2 = ((const uint4*)gl)[2], b3 = ((const uint4*)gl)[3];
        uint4* dh = (uint4*)(sQh + crow * QSTR + coff);
        uint4* dl = (uint4*)(sQl + crow * QSTR + coff);
        dh[0] = a0; dh[1] = a1; dh[2] = a2; dh[3] = a3;
        dl[0] = b0; dl[1] = b1; dl[2] = b2; dl[3] = b3;
    }
    __syncthreads();

    uint32_t qh[4][4], ql[4][4];
    {
        const uint32_t qoff = (uint32_t)(w * 16 + (g & 1) * 8 + lr) * QSTR
                            + (uint32_t)((g >> 1) * 8) * 2;
        #pragma unroll
        for (int ks = 0; ks < 4; ks++) {
            ldsm4(qh[ks], uQh + qoff + ks * 32);
            ldsm4(ql[ks], uQl + qoff + ks * 32);
        }
    }

    float accO[8][4];
    #pragma unroll
    for (int nt = 0; nt < 8; nt++)
        #pragma unroll
        for (int i = 0; i < 4; i++) accO[nt][i] = 0.f;
    float mrow[2] = {-1e30f, -1e30f};
    float lrow[2] = {0.f, 0.f};

    uint32_t koff[4];
    #pragma unroll
    for (int np = 0; np < 4; np++)
        koff[np] = (uint32_t)(np * 16 + (g >> 1) * 8 + lr) * QSTR
                 + (uint32_t)((g & 1) * 8) * 2;
    const uint32_t vrow = (uint32_t)((g & 1) * 8 + lr);
    const uint32_t vcol = (uint32_t)((g >> 1) * 8) * 2;

    const int ntiles = (r0 >> 6) + 2;   // kv tiles 0..(r0+64)/64
    for (int i = 0; i < ntiles; i++) {
        CP_WAIT(0);
        __syncthreads();
        if (i + 1 < ntiles) {
            attn_stage_kv(kvbase + (uint32_t)((i + 1) & 1) * AKV_STG,
                          base, (i + 1) * 64, t);
            CP_COMMIT();
        }
        const uint32_t st = kvbase + (uint32_t)(i & 1) * AKV_STG;
        const uint32_t uKh = st, uKl = st + AKV;
        const uint32_t uVh = st + 2 * AKV, uVl = st + 3 * AKV;
        const int j0 = i * 64;

        float accS[8][4];
        #pragma unroll
        for (int nt = 0; nt < 8; nt++)
            #pragma unroll
            for (int ii = 0; ii < 4; ii++) accS[nt][ii] = 0.f;

        #pragma unroll
        for (int ks = 0; ks < 4; ks++) {
            #pragma unroll
            for (int np = 0; np < 4; np++) {
                uint32_t kfh[4], kfl[4];
                ldsm4(kfh, uKh + koff[np] + ks * 32);
                ldsm4(kfl, uKl + koff[np] + ks * 32);
                #pragma unroll
                for (int hf = 0; hf < 2; hf++) {
                    const int nt = np * 2 + hf;
                    mma16816(accS[nt], qh[ks], kfh[hf * 2], kfh[hf * 2 + 1]);
                    mma16816(accS[nt], qh[ks], kfl[hf * 2], kfl[hf * 2 + 1]);
                    mma16816(accS[nt], ql[ks], kfh[hf * 2], kfh[hf * 2 + 1]);
                }
            }
        }

        // causal mask (global row/col); only tiles overlapping/after the slab
        if (j0 + 63 > wr0) {
            #pragma unroll
            for (int nt = 0; nt < 8; nt++)
                #pragma unroll
                for (int ii = 0; ii < 4; ii++) {
                    const int gcol = j0 + nt * 8 + qc * 2 + (ii & 1);
                    const int grow = wr0 + qr + (ii >> 1) * 8;
                    if (gcol > grow) accS[nt][ii] = -1e30f;
                }
        }

        // softmax in exp2 domain (log2e folded into q)
        float corr[2];
        #pragma unroll
        for (int hrow = 0; hrow < 2; hrow++) {
            float mx = -1e30f;
            #pragma unroll
            for (int nt = 0; nt < 8; nt++) {
                mx = fmaxf(mx, fmaxf(accS[nt][hrow * 2], accS[nt][hrow * 2 + 1]));
            }
            mx = fmaxf(mx, __shfl_xor_sync(0xffffffffu, mx, 1));
            mx = fmaxf(mx, __shfl_xor_sync(0xffffffffu, mx, 2));
            const float m_new = fmaxf(mrow[hrow], mx);
            corr[hrow] = ex2(mrow[hrow] - m_new);
            mrow[hrow] = m_new;
            float rs = 0.f;
            #pragma unroll
            for (int nt = 0; nt < 8; nt++) {
                float p0 = ex2(accS[nt][hrow * 2]     - m_new);
                float p1 = ex2(accS[nt][hrow * 2 + 1] - m_new);
                accS[nt][hrow * 2]     = p0;
                accS[nt][hrow * 2 + 1] = p1;
                rs += p0 + p1;
            }
            rs += __shfl_xor_sync(0xffffffffu, rs, 1);
            rs += __shfl_xor_sync(0xffffffffu, rs, 2);
            lrow[hrow] = lrow[hrow] * corr[hrow] + rs;
        }
        #pragma unroll
        for (int nt = 0; nt < 8; nt++) {
            accO[nt][0] *= corr[0]; accO[nt][1] *= corr[0];
            accO[nt][2] *= corr[1]; accO[nt][3] *= corr[1];
        }

        // O += P V  (P hi/lo, V hi/lo -> 3 terms)
        #pragma unroll
        for (int ks = 0; ks < 4; ks++) {
            uint32_t pfh[4], pfl[4];
            #pragma unroll
            for (int half = 0; half < 2; half++) {
                const int nt = ks * 2 + half;
                #pragma unroll
                for (int rh = 0; rh < 2; rh++) {
                    float v0 = accS[nt][rh * 2], v1 = accS[nt][rh * 2 + 1];
                    float h0 = __bfloat162float(__float2bfloat16(v0));
                    float h1 = __bfloat162float(__float2bfloat16(v1));
                    pfh[half * 2 + rh] = packbf(h0, h1);
                    pfl[half * 2 + rh] = packbf(v0 - h0, v1 - h1);
                }
            }
            #pragma unroll
            for (int np = 0; np < 4; np++) {
                uint32_t vfh[4], vfl[4];
                const uint32_t va = (vrow + ks * 16) * QSTR + np * 32 + vcol;
                ldsm4t(vfh, uVh + va);
                ldsm4t(vfl, uVl + va);
                #pragma unroll
                for (int hf = 0; hf < 2; hf++) {
                    const int nt = np * 2 + hf;
                    mma16816(accO[nt], pfh, vfh[hf * 2], vfh[hf * 2 + 1]);
                    mma16816(accO[nt], pfh, vfl[hf * 2], vfl[hf * 2 + 1]);
                    mma16816(accO[nt], pfl, vfh[hf * 2], vfh[hf * 2 + 1]);
                }
            }
        }
    }

    const float inv0 = 1.f / lrow[0];
    const float inv1 = 1.f / lrow[1];
    const int b = bh >> 4, hh = bh & 15;
    #pragma unroll
    for (int nt = 0; nt < 8; nt++) {
        const int d = hh * 64 + nt * 8 + qc * 2;
        #pragma unroll
        for (int rh = 0; rh < 2; rh++) {
            const float inv = rh ? inv1 : inv0;
            const int row = wr0 + qr + rh * 8;
            const size_t idx = (size_t)(b * T_ + row) * C_ + d;
            float v0 = accO[nt][rh * 2] * inv;
            float v1 = accO[nt][rh * 2 + 1] * inv;
            float h0 = __bfloat162float(__float2bfloat16(v0));
            float h1 = __bfloat162float(__float2bfloat16(v1));
            *(uint32_t*)&g_ahi[idx] = packbf(h0, h1);
            *(uint32_t*)&g_alo[idx] = packbf(v0 - h0, v1 - h1);
        }
    }
}

// ---------------------------------------------------------------------------
extern "C" void kernel_launch(void* const* d_in, const int* in_sizes, int n_in,
                              void* d_out, int out_size)
{
    const float* x  = (const float*)d_in[0];
    const float* Wq = (const float*)d_in[1];
    const float* Wk = (const float*)d_in[2];
    const float* Wv = (const float*)d_in[3];
    const float* Wo = (const float*)d_in[4];
    const float* bo = (const float*)d_in[5];
    float* out = (float*)d_out;

    __nv_bfloat16 *xhi, *xlo, *wohi, *wolo;
    cudaGetSymbolAddress((void**)&xhi,  g_xhi);
    cudaGetSymbolAddress((void**)&xlo,  g_xlo);
    cudaGetSymbolAddress((void**)&wohi, g_wohi);
    cudaGetSymbolAddress((void**)&wolo, g_wolo);

    cudaFuncSetAttribute(qkv_mma_kernel,
        cudaFuncAttributeMaxDynamicSharedMemorySize, GSMEM);
    cudaFuncSetAttribute(proj_mma_kernel,
        cudaFuncAttributeMaxDynamicSharedMemorySize, GSMEM);
    cudaFuncSetAttribute(attn_hmma_kernel,
        cudaFuncAttributeMaxDynamicSharedMemorySize, ASMEM);

    split_kernel<<<(B_ * T_ * C_ / 4 + 255) / 256, 256>>>(x, xhi, xlo, B_ * T_ * C_ / 4);
    split_wqkv_kernel<<<dim3(HS_ * C_ / 256, 48), 256>>>(Wq, Wk, Wv);
    split_kernel<<<(C_ * C_ / 4 + 255) / 256, 256>>>(Wo, wohi, wolo, C_ * C_ / 4);

    qkv_mma_kernel<<<dim3(B_ * T_ / 128, 3 * C_ / 128), 256, GSMEM>>>();

    attn_hmma_kernel<<<dim3(T_ / 128, B_ * H_), 256, ASMEM>>>();

    proj_mma_kernel<<<dim3(B_ * T_ / 128, C_ / 128), 256, GSMEM>>>(bo, out);
}